// round 6
// baseline (speedup 1.0000x reference)
#include <cuda_runtime.h>
#include <cuda_bf16.h>
#include <cstdint>

typedef __nv_bfloat16 bf16;

#define MB 8192       // B*T
#define TT 2048
#define BH 64         // B*H

// ---------------- device scratch ----------------
__device__ bf16  g_xe [(size_t)MB * 2048];        // x split   [hi(1024) | lo(1024)] row-major
__device__ bf16  g_wat[(size_t)3072 * 2048];      // W_attn^T split, n-major
__device__ bf16  g_wpt[(size_t)1024 * 2048];      // W_proj^T split, n-major
__device__ float g_qkv[(size_t)MB * 3072];        // qkv fp32
__device__ bf16  g_qe [(size_t)BH * TT * 128];    // Q rope split [hi(64)|lo(64)], pre-scaled
__device__ bf16  g_ke [(size_t)BH * TT * 128];    // K rope split
__device__ bf16  g_vt [(size_t)BH * 64 * 2 * TT]; // V dim-major [hi(T)|lo(T)] per dim
__device__ bf16  g_ye [(size_t)MB * 2048];        // attention out split

// ---------------- helpers ----------------
__device__ __forceinline__ void cpa16(void* s, const void* g) {
    uint32_t sa = (uint32_t)__cvta_generic_to_shared(s);
    asm volatile("cp.async.ca.shared.global [%0], [%1], 16;\n" :: "r"(sa), "l"(g));
}
__device__ __forceinline__ void cp_commit() { asm volatile("cp.async.commit_group;\n"); }
__device__ __forceinline__ void cp_wait1()  { asm volatile("cp.async.wait_group 1;\n"); }
__device__ __forceinline__ void cp_wait2()  { asm volatile("cp.async.wait_group 2;\n"); }

__device__ __forceinline__ void ldsm4(uint32_t* r, const void* p) {
    uint32_t a = (uint32_t)__cvta_generic_to_shared(p);
    asm volatile("ldmatrix.sync.aligned.m8n8.x4.shared.b16 {%0,%1,%2,%3}, [%4];"
                 : "=r"(r[0]), "=r"(r[1]), "=r"(r[2]), "=r"(r[3]) : "r"(a));
}

__device__ __forceinline__ void mma16816(float* c, const uint32_t* a, const uint32_t* b) {
    asm volatile("mma.sync.aligned.m16n8k16.row.col.f32.bf16.bf16.f32 "
        "{%0,%1,%2,%3}, {%4,%5,%6,%7}, {%8,%9}, {%0,%1,%2,%3};"
        : "+f"(c[0]), "+f"(c[1]), "+f"(c[2]), "+f"(c[3])
        : "r"(a[0]), "r"(a[1]), "r"(a[2]), "r"(a[3]), "r"(b[0]), "r"(b[1]));
}

__device__ __forceinline__ float ex2(float x) {
    float y; asm("ex2.approx.f32 %0, %1;" : "=f"(y) : "f"(x)); return y;
}

__device__ __forceinline__ uint32_t pack_hi_lo(float a, float b, uint32_t& lo) {
    bf16 ha = __float2bfloat16(a), hb = __float2bfloat16(b);
    bf16 la = __float2bfloat16(a - __bfloat162float(ha));
    bf16 lb = __float2bfloat16(b - __bfloat162float(hb));
    __nv_bfloat162 h2; h2.x = ha; h2.y = hb;
    __nv_bfloat162 l2; l2.x = la; l2.y = lb;
    lo = *(uint32_t*)&l2;
    return *(uint32_t*)&h2;
}

// ---------------- conversion kernels ----------------
__global__ void conv_x_kernel(const float* __restrict__ x) {
    int idx = blockIdx.x * 256 + threadIdx.x;
    if (idx >= MB * 1024) return;
    int m = idx >> 10, c = idx & 1023;
    float v = x[idx];
    bf16 h = __float2bfloat16(v);
    bf16 l = __float2bfloat16(v - __bfloat162float(h));
    g_xe[(size_t)m * 2048 + c] = h;
    g_xe[(size_t)m * 2048 + 1024 + c] = l;
}

template <int WSEL>
__global__ void conv_w_kernel(const float* __restrict__ W, int N) {
    bf16* dst = WSEL ? g_wpt : g_wat;
    __shared__ float ws[32][33];
    int n0 = blockIdx.x * 32, k0 = blockIdx.y * 32;
    int tx = threadIdx.x & 31, ty = threadIdx.x >> 5;
#pragma unroll
    for (int i = 0; i < 4; i++) {
        int k = k0 + ty + i * 8;
        ws[ty + i * 8][tx] = W[(size_t)k * N + n0 + tx];
    }
    __syncthreads();
#pragma unroll
    for (int i = 0; i < 4; i++) {
        int n = n0 + ty + i * 8, k = k0 + tx;
        float v = ws[tx][ty + i * 8];
        bf16 h = __float2bfloat16(v);
        bf16 l = __float2bfloat16(v - __bfloat162float(h));
        dst[(size_t)n * 2048 + k] = h;
        dst[(size_t)n * 2048 + 1024 + k] = l;
    }
}

// ---------------- bf16x3 GEMM, CTA 128x128, 4 warps of 64x64, 4-stage, 2 CTA/SM ----------------
// smem per stage (bf16 elems): Ahi[128][24] Alo[128][24] Bhi[128][24] Blo[128][24]
#define GAH 0
#define GAL 3072
#define GBH 6144
#define GBL 9216
#define GST 12288   // bf16 elems per stage (24576 B)
template <int MODE, int N>
__global__ __launch_bounds__(128, 2) void gemm_bf16x3(float* __restrict__ Cext) {
    const bf16* A  = MODE ? g_ye  : g_xe;
    const bf16* Bt = MODE ? g_wpt : g_wat;
    float*      C  = MODE ? Cext  : g_qkv;

    extern __shared__ bf16 sm[];   // 4 stages x GST

    const int tid = threadIdx.x;
    const int m0 = blockIdx.y * 128, n0 = blockIdx.x * 128;
    const int wid = tid >> 5, lane = tid & 31, g = lane >> 2, q = lane & 3;
    const int wm = (wid & 1) * 64, wn = (wid >> 1) * 64;

    const int arow = (lane & 7) + ((lane >> 3) & 1) * 8;
    const int acs  = (lane >> 4) * 8;
    const int brow = (lane & 7) + (lane >> 4) * 8;
    const int bcs  = ((lane >> 3) & 1) * 8;

    float acc[4][8][4];
#pragma unroll
    for (int i = 0; i < 4; i++)
#pragma unroll
        for (int j = 0; j < 8; j++)
#pragma unroll
            for (int r = 0; r < 4; r++) acc[i][j][r] = 0.f;

    auto load_tile = [&](int t, int stage) {
        const int kk = t * 16;
        bf16* st = sm + stage * GST;
        const bf16* ap = A  + (size_t)(m0 + tid) * 2048 + kk;
        const bf16* bp = Bt + (size_t)(n0 + tid) * 2048 + kk;
        cpa16(st + GAH + tid * 24,     ap);
        cpa16(st + GAH + tid * 24 + 8, ap + 8);
        cpa16(st + GAL + tid * 24,     ap + 1024);
        cpa16(st + GAL + tid * 24 + 8, ap + 1032);
        cpa16(st + GBH + tid * 24,     bp);
        cpa16(st + GBH + tid * 24 + 8, bp + 8);
        cpa16(st + GBL + tid * 24,     bp + 1024);
        cpa16(st + GBL + tid * 24 + 8, bp + 1032);
        cp_commit();
    };

    load_tile(0, 0);
    load_tile(1, 1);
    load_tile(2, 2);

    for (int i = 0; i < 64; i++) {
        cp_wait2();
        __syncthreads();
        if (i + 3 < 64) load_tile(i + 3, (i + 3) & 3);
        else cp_commit();

        const bf16* st = sm + (i & 3) * GST;
        const bf16 (*Ah)[24] = (const bf16(*)[24])(st + GAH);
        const bf16 (*Al)[24] = (const bf16(*)[24])(st + GAL);
        const bf16 (*Bh)[24] = (const bf16(*)[24])(st + GBH);
        const bf16 (*Bl)[24] = (const bf16(*)[24])(st + GBL);

        uint32_t ah[4][4], al[4][4], bh[4][4], bl[4][4];
#pragma unroll
        for (int ma = 0; ma < 4; ma++) ldsm4(ah[ma], &Ah[wm + ma * 16 + arow][acs]);
#pragma unroll
        for (int nb = 0; nb < 4; nb++) ldsm4(bh[nb], &Bh[wn + nb * 16 + brow][bcs]);
#pragma unroll
        for (int nb = 0; nb < 4; nb++) ldsm4(bl[nb], &Bl[wn + nb * 16 + brow][bcs]);
#pragma unroll
        for (int ma = 0; ma < 4; ma++) ldsm4(al[ma], &Al[wm + ma * 16 + arow][acs]);

        // seg 0: Ahi*Bhi
#pragma unroll
        for (int na = 0; na < 8; na++) {
            const uint32_t* bb = &bh[na >> 1][(na & 1) * 2];
#pragma unroll
            for (int ma = 0; ma < 4; ma++) mma16816(acc[ma][na], ah[ma], bb);
        }
        // seg 1: Ahi*Blo
#pragma unroll
        for (int na = 0; na < 8; na++) {
            const uint32_t* bb = &bl[na >> 1][(na & 1) * 2];
#pragma unroll
            for (int ma = 0; ma < 4; ma++) mma16816(acc[ma][na], ah[ma], bb);
        }
        // seg 2: Alo*Bhi
#pragma unroll
        for (int na = 0; na < 8; na++) {
            const uint32_t* bb = &bh[na >> 1][(na & 1) * 2];
#pragma unroll
            for (int ma = 0; ma < 4; ma++) mma16816(acc[ma][na], al[ma], bb);
        }
        __syncthreads();
    }

#pragma unroll
    for (int ma = 0; ma < 4; ma++) {
        int r = m0 + wm + ma * 16 + g;
#pragma unroll
        for (int na = 0; na < 8; na++) {
            int c = n0 + wn + na * 8 + 2 * q;
            *(float2*)&C[(size_t)r * N + c]       = make_float2(acc[ma][na][0], acc[ma][na][1]);
            *(float2*)&C[(size_t)(r + 8) * N + c] = make_float2(acc[ma][na][2], acc[ma][na][3]);
        }
    }
}

// ---------------- RoPE (Q,K only); Q pre-scaled by 0.125*log2(e) ----------------
__global__ void rope_kernel() {
    int idx = blockIdx.x * 256 + threadIdx.x;
    if (idx >= MB * 1024) return;
    int d = idx & 63, h = (idx >> 6) & 15, t = (idx >> 10) & 2047, b = idx >> 21;

    size_t base = (size_t)(b * TT + t) * 3072 + h * 64;
    float qv = g_qkv[base + d];
    float kv = g_qkv[base + 1024 + d];
    int dro = (d < 32) ? d + 32 : d - 32;
    float qo = g_qkv[base + dro];
    float ko = g_qkv[base + 1024 + dro];
    float sgn = (d < 32) ? -1.f : 1.f;

    int j = d & 31;
    float inv = exp2f(-(float)(2 * j) * (13.287712379549449f / 64.f));
    float ang = (float)t * inv, sn, cs;
    sincosf(ang, &sn, &cs);

    float qr = (qv * cs + sgn * qo * sn) * 0.18033688011112043f;  // 1/8 * log2(e)
    float kr = kv * cs + sgn * ko * sn;

    int bh = b * 16 + h;
    size_t ob = ((size_t)bh * TT + t) * 128;
    bf16 hh, ll;
    hh = __float2bfloat16(qr); ll = __float2bfloat16(qr - __bfloat162float(hh));
    g_qe[ob + d] = hh; g_qe[ob + 64 + d] = ll;
    hh = __float2bfloat16(kr); ll = __float2bfloat16(kr - __bfloat162float(hh));
    g_ke[ob + d] = hh; g_ke[ob + 64 + d] = ll;
}

// ---------------- V transpose to dim-major split ----------------
__global__ void vtrans_kernel() {
    __shared__ float vs[32][65];
    int bh = blockIdx.y, t0 = blockIdx.x * 32;
    int b = bh >> 4, h = bh & 15;
    int tid = threadIdx.x;
#pragma unroll
    for (int i = 0; i < 8; i++) {
        int idx = i * 256 + tid;
        int t = idx >> 6, d = idx & 63;
        vs[t][d] = g_qkv[(size_t)(b * TT + t0 + t) * 3072 + 2048 + h * 64 + d];
    }
    __syncthreads();
    int t = tid & 31;
#pragma unroll
    for (int i = 0; i < 8; i++) {
        int d = i * 8 + (tid >> 5);
        float v = vs[t][d];
        bf16 hh = __float2bfloat16(v);
        bf16 ll = __float2bfloat16(v - __bfloat162float(hh));
        size_t vb = ((size_t)bh * 64 + d) * (2 * TT) + t0 + t;
        g_vt[vb] = hh;
        g_vt[vb + TT] = ll;
    }
}

// ---------------- flash attention, bf16x3 mma, segment-fused, 3-stage ----------------
#define AST 34816   // bytes per stage (Ks 64x136 + Vs 64x136, bf16)
__global__ __launch_bounds__(256) void attn_kernel() {
    extern __shared__ char smraw[];

    const int tid = threadIdx.x, wid = tid >> 5, lane = tid & 31;
    const int g = lane >> 2, q = lane & 3;
    const int bh = blockIdx.y, q0 = blockIdx.x * 128;

    const int krow = (lane & 7) + (lane >> 4) * 8;
    const int kcs  = ((lane >> 3) & 1) * 8;

    const bf16* qbase = g_qe + ((size_t)bh * TT + q0) * 128;
    const bf16* kbase = g_ke + (size_t)bh * TT * 128;
    const bf16* vbase = g_vt + (size_t)bh * 64 * (2 * TT);

    uint32_t qf[8][4];
    {
        int r = wid * 16 + g;
#pragma unroll
        for (int ka = 0; ka < 8; ka++) {
            int c = ka * 16 + 2 * q;
            qf[ka][0] = *(const uint32_t*)&qbase[(size_t)r * 128 + c];
            qf[ka][1] = *(const uint32_t*)&qbase[(size_t)(r + 8) * 128 + c];
            qf[ka][2] = *(const uint32_t*)&qbase[(size_t)r * 128 + c + 8];
            qf[ka][3] = *(const uint32_t*)&qbase[(size_t)(r + 8) * 128 + c + 8];
        }
    }

    float o[8][4];
#pragma unroll
    for (int na = 0; na < 8; na++)
#pragma unroll
        for (int r2 = 0; r2 < 4; r2++) o[na][r2] = 0.f;
    float mrow0 = -1e30f, mrow1 = -1e30f, lr0 = 0.f, lr1 = 0.f;

    const int lrow = tid >> 2;
    const int lp0  = (tid & 3) * 4;

    auto load_tile = [&](int jt, int buf) {
        bf16 (*Ks)[136] = (bf16(*)[136])(smraw + buf * AST);
        bf16 (*Vs)[136] = (bf16(*)[136])(smraw + buf * AST + 17408);
        int j0 = jt * 64;
#pragma unroll
        for (int c2 = 0; c2 < 4; c2++) {
            int part = lp0 + c2;
            cpa16(&Ks[lrow][part * 8], kbase + (size_t)(j0 + lrow) * 128 + part * 8);
            const bf16* vsrc = (part < 8)
                ? (vbase + (size_t)lrow * (2 * TT) + j0 + part * 8)
                : (vbase + (size_t)lrow * (2 * TT) + TT + j0 + (part - 8) * 8);
            cpa16(&Vs[lrow][part * 8], vsrc);
        }
        cp_commit();
    };

    load_tile(0, 0);
    load_tile(1, 1);

    for (int jt = 0; jt < 32; jt++) {
        cp_wait1();
        __syncthreads();
        if (jt + 2 < 32) load_tile(jt + 2, (jt + 2) % 3);
        else cp_commit();

        const int buf = jt % 3;
        const bf16 (*Ks)[136] = (const bf16(*)[136])(smraw + buf * AST);
        const bf16 (*Vs)[136] = (const bf16(*)[136])(smraw + buf * AST + 17408);

        float s[8][4];
#pragma unroll
        for (int na = 0; na < 8; na++)
#pragma unroll
            for (int r2 = 0; r2 < 4; r2++) s[na][r2] = 0.f;

#pragma unroll
        for (int ks = 0; ks < 4; ks++) {
#pragma unroll
            for (int pr = 0; pr < 4; pr++) {
                uint32_t b4h[4], b4l[4];
                ldsm4(b4h, &Ks[pr * 16 + krow][ks * 16 + kcs]);
                ldsm4(b4l, &Ks[pr * 16 + krow][64 + ks * 16 + kcs]);
                mma16816(s[2 * pr],     qf[ks], b4h);
                mma16816(s[2 * pr + 1], qf[ks], b4h + 2);
                mma16816(s[2 * pr],     qf[ks], b4l);
                mma16816(s[2 * pr + 1], qf[ks], b4l + 2);
                mma16816(s[2 * pr],     qf[4 + ks], b4h);
                mma16816(s[2 * pr + 1], qf[4 + ks], b4h + 2);
            }
        }

        float nm0 = mrow0, nm1 = mrow1;
#pragma unroll
        for (int na = 0; na < 8; na++) {
            nm0 = fmaxf(nm0, fmaxf(s[na][0], s[na][1]));
            nm1 = fmaxf(nm1, fmaxf(s[na][2], s[na][3]));
        }
        nm0 = fmaxf(nm0, __shfl_xor_sync(0xffffffffu, nm0, 1));
        nm0 = fmaxf(nm0, __shfl_xor_sync(0xffffffffu, nm0, 2));
        nm1 = fmaxf(nm1, __shfl_xor_sync(0xffffffffu, nm1, 1));
        nm1 = fmaxf(nm1, __shfl_xor_sync(0xffffffffu, nm1, 2));
        float corr0 = ex2(mrow0 - nm0), corr1 = ex2(mrow1 - nm1);
        mrow0 = nm0; mrow1 = nm1;
        lr0 *= corr0; lr1 *= corr1;
#pragma unroll
        for (int na = 0; na < 8; na++) {
            o[na][0] *= corr0; o[na][1] *= corr0;
            o[na][2] *= corr1; o[na][3] *= corr1;
        }

        uint32_t phA[8], phB[8], plA[8], plB[8];
#pragma unroll
        for (int na = 0; na < 8; na++) {
            float p0 = ex2(s[na][0] - nm0), p1 = ex2(s[na][1] - nm0);
            float p2 = ex2(s[na][2] - nm1), p3 = ex2(s[na][3] - nm1);
            lr0 += p0 + p1; lr1 += p2 + p3;
            phA[na] = pack_hi_lo(p0, p1, plA[na]);
            phB[na] = pack_hi_lo(p2, p3, plB[na]);
        }

#pragma unroll
        for (int ks = 0; ks < 4; ks++) {
            uint32_t afh[4] = { phA[2 * ks], phB[2 * ks], phA[2 * ks + 1], phB[2 * ks + 1] };
            uint32_t afl[4] = { plA[2 * ks], plB[2 * ks], plA[2 * ks + 1], plB[2 * ks + 1] };
#pragma unroll
            for (int pr = 0; pr < 4; pr++) {
                uint32_t b4h[4], b4l[4];
                ldsm4(b4h, &Vs[pr * 16 + krow][ks * 16 + kcs]);
                ldsm4(b4l, &Vs[pr * 16 + krow][64 + ks * 16 + kcs]);
                mma16816(o[2 * pr],     afh, b4h);
                mma16816(o[2 * pr + 1], afh, b4h + 2);
                mma16816(o[2 * pr],     afh, b4l);
                mma16816(o[2 * pr + 1], afh, b4l + 2);
                mma16816(o[2 * pr],     afl, b4h);
                mma16816(o[2 * pr + 1], afl, b4h + 2);
            }
        }
    }

    lr0 += __shfl_xor_sync(0xffffffffu, lr0, 1);
    lr0 += __shfl_xor_sync(0xffffffffu, lr0, 2);
    lr1 += __shfl_xor_sync(0xffffffffu, lr1, 1);
    lr1 += __shfl_xor_sync(0xffffffffu, lr1, 2);
    float inv0 = 1.f / lr0, inv1 = 1.f / lr1;

    int b = bh >> 4, h = bh & 15;
    int t0 = q0 + wid * 16 + g;
    size_t row0 = (size_t)(b * TT + t0) * 2048;
    size_t row1 = (size_t)(b * TT + t0 + 8) * 2048;
#pragma unroll
    for (int na = 0; na < 8; na++) {
        int c = h * 64 + na * 8 + 2 * q;
        uint32_t lo, hi;
        hi = pack_hi_lo(o[na][0] * inv0, o[na][1] * inv0, lo);
        *(uint32_t*)&g_ye[row0 + c] = hi;
        *(uint32_t*)&g_ye[row0 + 1024 + c] = lo;
        hi = pack_hi_lo(o[na][2] * inv1, o[na][3] * inv1, lo);
        *(uint32_t*)&g_ye[row1 + c] = hi;
        *(uint32_t*)&g_ye[row1 + 1024 + c] = lo;
    }
}

// ---------------- launch ----------------
extern "C" void kernel_launch(void* const* d_in, const int* in_sizes, int n_in,
                              void* d_out, int out_size)
{
    const float* x      = (const float*)d_in[0];
    const float* W_attn = (const float*)d_in[1];
    const float* W_proj = (const float*)d_in[2];
    float* out = (float*)d_out;

    cudaFuncSetAttribute(gemm_bf16x3<0, 3072>, cudaFuncAttributeMaxDynamicSharedMemorySize, 98304);
    cudaFuncSetAttribute(gemm_bf16x3<1, 1024>, cudaFuncAttributeMaxDynamicSharedMemorySize, 98304);
    cudaFuncSetAttribute(attn_kernel, cudaFuncAttributeMaxDynamicSharedMemorySize, 104448);

    conv_x_kernel<<<MB * 1024 / 256, 256>>>(x);
    conv_w_kernel<0><<<dim3(96, 32), 256>>>(W_attn, 3072);
    conv_w_kernel<1><<<dim3(32, 32), 256>>>(W_proj, 1024);
    gemm_bf16x3<0, 3072><<<dim3(24, 64), 128, 98304>>>(nullptr);
    rope_kernel<<<MB * 1024 / 256, 256>>>();
    vtrans_kernel<<<dim3(64, 64), 256>>>();
    attn_kernel<<<dim3(16, 64), 256, 104448>>>();
    gemm_bf16x3<1, 1024><<<dim3(8, 64), 128, 98304>>>(out);
}

// round 8
// speedup vs baseline: 1.1275x; 1.1275x over previous
#include <cuda_runtime.h>
#include <cuda_bf16.h>
#include <cstdint>

typedef __nv_bfloat16 bf16;

#define MB 8192       // B*T
#define TT 2048
#define BH 64         // B*H

// ---------------- device scratch ----------------
__device__ bf16  g_xe [(size_t)MB * 2048];        // x split   [hi(1024) | lo(1024)] row-major
__device__ bf16  g_wat[(size_t)3072 * 2048];      // W_attn^T split, n-major
__device__ bf16  g_wpt[(size_t)1024 * 2048];      // W_proj^T split, n-major
__device__ float g_qkv[(size_t)MB * 3072];        // qkv fp32
__device__ bf16  g_qe [(size_t)BH * TT * 128];    // Q rope split [hi(64)|lo(64)], pre-scaled
__device__ bf16  g_ke [(size_t)BH * TT * 128];    // K rope split
__device__ bf16  g_vt [(size_t)BH * 64 * 2 * TT]; // V dim-major [hi(T)|lo(T)] per dim
__device__ bf16  g_ye [(size_t)MB * 2048];        // attention out split

// ---------------- helpers ----------------
__device__ __forceinline__ void cpa16(void* s, const void* g) {
    uint32_t sa = (uint32_t)__cvta_generic_to_shared(s);
    asm volatile("cp.async.cg.shared.global [%0], [%1], 16;\n" :: "r"(sa), "l"(g));
}
__device__ __forceinline__ void cp_commit() { asm volatile("cp.async.commit_group;\n"); }
__device__ __forceinline__ void cp_wait1()  { asm volatile("cp.async.wait_group 1;\n"); }
__device__ __forceinline__ void cp_wait2()  { asm volatile("cp.async.wait_group 2;\n"); }

__device__ __forceinline__ void ldsm4(uint32_t* r, const void* p) {
    uint32_t a = (uint32_t)__cvta_generic_to_shared(p);
    asm volatile("ldmatrix.sync.aligned.m8n8.x4.shared.b16 {%0,%1,%2,%3}, [%4];"
                 : "=r"(r[0]), "=r"(r[1]), "=r"(r[2]), "=r"(r[3]) : "r"(a));
}

__device__ __forceinline__ void mma16816(float* c, const uint32_t* a, const uint32_t* b) {
    asm volatile("mma.sync.aligned.m16n8k16.row.col.f32.bf16.bf16.f32 "
        "{%0,%1,%2,%3}, {%4,%5,%6,%7}, {%8,%9}, {%0,%1,%2,%3};"
        : "+f"(c[0]), "+f"(c[1]), "+f"(c[2]), "+f"(c[3])
        : "r"(a[0]), "r"(a[1]), "r"(a[2]), "r"(a[3]), "r"(b[0]), "r"(b[1]));
}

__device__ __forceinline__ float ex2(float x) {
    float y; asm("ex2.approx.f32 %0, %1;" : "=f"(y) : "f"(x)); return y;
}

// rn-based split (used outside hot loops)
__device__ __forceinline__ uint32_t pack_hi_lo(float a, float b, uint32_t& lo) {
    bf16 ha = __float2bfloat16(a), hb = __float2bfloat16(b);
    bf16 la = __float2bfloat16(a - __bfloat162float(ha));
    bf16 lb = __float2bfloat16(b - __bfloat162float(hb));
    __nv_bfloat162 h2; h2.x = ha; h2.y = hb;
    __nv_bfloat162 l2; l2.x = la; l2.y = lb;
    lo = *(uint32_t*)&l2;
    return *(uint32_t*)&h2;
}

// truncation-based split: hi = exact top bits (bitmask), lo = residual (exact via FSUB)
__device__ __forceinline__ uint32_t pack_trunc(float a, float b, uint32_t& lo) {
    uint32_t ha = __float_as_uint(a) & 0xFFFF0000u;
    uint32_t hb = __float_as_uint(b) & 0xFFFF0000u;
    uint32_t hi;
    asm("prmt.b32 %0, %1, %2, 0x7632;" : "=r"(hi) : "r"(ha), "r"(hb));
    float la = a - __uint_as_float(ha);
    float lb = b - __uint_as_float(hb);
    asm("cvt.rn.bf16x2.f32 %0, %1, %2;" : "=r"(lo) : "f"(lb), "f"(la));
    return hi;
}

// ---------------- conversion kernels ----------------
__global__ void conv_x_kernel(const float* __restrict__ x) {
    int idx = blockIdx.x * 256 + threadIdx.x;
    if (idx >= MB * 1024) return;
    int m = idx >> 10, c = idx & 1023;
    float v = x[idx];
    bf16 h = __float2bfloat16(v);
    bf16 l = __float2bfloat16(v - __bfloat162float(h));
    g_xe[(size_t)m * 2048 + c] = h;
    g_xe[(size_t)m * 2048 + 1024 + c] = l;
}

template <int WSEL>
__global__ void conv_w_kernel(const float* __restrict__ W, int N) {
    bf16* dst = WSEL ? g_wpt : g_wat;
    __shared__ float ws[32][33];
    int n0 = blockIdx.x * 32, k0 = blockIdx.y * 32;
    int tx = threadIdx.x & 31, ty = threadIdx.x >> 5;
#pragma unroll
    for (int i = 0; i < 4; i++) {
        int k = k0 + ty + i * 8;
        ws[ty + i * 8][tx] = W[(size_t)k * N + n0 + tx];
    }
    __syncthreads();
#pragma unroll
    for (int i = 0; i < 4; i++) {
        int n = n0 + ty + i * 8, k = k0 + tx;
        float v = ws[tx][ty + i * 8];
        bf16 h = __float2bfloat16(v);
        bf16 l = __float2bfloat16(v - __bfloat162float(h));
        dst[(size_t)n * 2048 + k] = h;
        dst[(size_t)n * 2048 + 1024 + k] = l;
    }
}

// ---------------- bf16x3 GEMM, segment-fused: 64 k16 steps, 4-stage pipeline ----------------
// smem per stage: Ahi/Alo/Bhi/Blo, each 128x16 (+8 pad) bf16
#define GST 12288   // bf16 elems per stage: 4 * 128 * 24
template <int MODE, int N>
__global__ __launch_bounds__(256, 2) void gemm_bf16x3(float* __restrict__ Cext) {
    const bf16* A  = MODE ? g_ye  : g_xe;
    const bf16* Bt = MODE ? g_wpt : g_wat;
    float*      C  = MODE ? Cext  : g_qkv;

    extern __shared__ bf16 sm[];   // 4 stages x GST

    const int tid = threadIdx.x;
    const int m0 = blockIdx.y * 128, n0 = blockIdx.x * 128;
    const int wid = tid >> 5, lane = tid & 31, g = lane >> 2, q = lane & 3;
    const int wm = (wid & 1) * 64, wn = (wid >> 1) * 32;

    const int arow = (lane & 7) + ((lane >> 3) & 1) * 8;
    const int acs  = (lane >> 4) * 8;
    const int brow = (lane & 7) + (lane >> 4) * 8;
    const int bcs  = ((lane >> 3) & 1) * 8;

    float acc[4][4][4];
#pragma unroll
    for (int i = 0; i < 4; i++)
#pragma unroll
        for (int j = 0; j < 4; j++)
#pragma unroll
            for (int r = 0; r < 4; r++) acc[i][j][r] = 0.f;

    const int lrow = tid >> 1;          // 0..127
    const int lhalf = (tid & 1) * 8;    // which 16B of the 32B row

    auto load_tile = [&](int t, int stage) {
        const int kk = t * 16;
        bf16* st = sm + stage * GST;
        const bf16* arow_p = A  + (size_t)(m0 + lrow) * 2048 + kk + lhalf;
        const bf16* brow_p = Bt + (size_t)(n0 + lrow) * 2048 + kk + lhalf;
        cpa16(st +        lrow * 24 + lhalf, arow_p);          // Ahi
        cpa16(st + 3072 + lrow * 24 + lhalf, arow_p + 1024);   // Alo
        cpa16(st + 6144 + lrow * 24 + lhalf, brow_p);          // Bhi
        cpa16(st + 9216 + lrow * 24 + lhalf, brow_p + 1024);   // Blo
        cp_commit();
    };

    load_tile(0, 0);
    load_tile(1, 1);
    load_tile(2, 2);

    for (int i = 0; i < 64; i++) {
        cp_wait2();
        __syncthreads();
        if (i + 3 < 64) load_tile(i + 3, (i + 3) & 3);
        else cp_commit();

        const bf16* st = sm + (i & 3) * GST;
        const bf16 (*Ah)[24] = (const bf16(*)[24])(st);
        const bf16 (*Al)[24] = (const bf16(*)[24])(st + 3072);
        const bf16 (*Bh)[24] = (const bf16(*)[24])(st + 6144);
        const bf16 (*Bl)[24] = (const bf16(*)[24])(st + 9216);

        uint32_t ah[4][4], al[4][4], bh[2][4], bl[2][4];
#pragma unroll
        for (int ma = 0; ma < 4; ma++) ldsm4(ah[ma], &Ah[wm + ma * 16 + arow][acs]);
        ldsm4(bh[0], &Bh[wn + 0  + brow][bcs]);
        ldsm4(bh[1], &Bh[wn + 16 + brow][bcs]);
        ldsm4(bl[0], &Bl[wn + 0  + brow][bcs]);
        ldsm4(bl[1], &Bl[wn + 16 + brow][bcs]);
#pragma unroll
        for (int ma = 0; ma < 4; ma++) ldsm4(al[ma], &Al[wm + ma * 16 + arow][acs]);

        // seg 0: Ahi*Bhi
#pragma unroll
        for (int na = 0; na < 4; na++) {
            const uint32_t* bb = &bh[na >> 1][(na & 1) * 2];
#pragma unroll
            for (int ma = 0; ma < 4; ma++) mma16816(acc[ma][na], ah[ma], bb);
        }
        // seg 1: Ahi*Blo
#pragma unroll
        for (int na = 0; na < 4; na++) {
            const uint32_t* bb = &bl[na >> 1][(na & 1) * 2];
#pragma unroll
            for (int ma = 0; ma < 4; ma++) mma16816(acc[ma][na], ah[ma], bb);
        }
        // seg 2: Alo*Bhi
#pragma unroll
        for (int na = 0; na < 4; na++) {
            const uint32_t* bb = &bh[na >> 1][(na & 1) * 2];
#pragma unroll
            for (int ma = 0; ma < 4; ma++) mma16816(acc[ma][na], al[ma], bb);
        }
        __syncthreads();
    }

#pragma unroll
    for (int ma = 0; ma < 4; ma++) {
        int r = m0 + wm + ma * 16 + g;
#pragma unroll
        for (int na = 0; na < 4; na++) {
            int c = n0 + wn + na * 8 + 2 * q;
            *(float2*)&C[(size_t)r * N + c]       = make_float2(acc[ma][na][0], acc[ma][na][1]);
            *(float2*)&C[(size_t)(r + 8) * N + c] = make_float2(acc[ma][na][2], acc[ma][na][3]);
        }
    }
}

// ---------------- RoPE (Q,K), paired halves; Q pre-scaled by 0.125*log2(e) ----------------
__global__ void rope_kernel() {
    int idx = blockIdx.x * 256 + threadIdx.x;        // over B*T*H*32 = 4194304
    if (idx >= MB * 512) return;
    int j = idx & 31, h = (idx >> 5) & 15, t = (idx >> 9) & 2047, b = idx >> 20;

    size_t base = (size_t)(b * TT + t) * 3072 + h * 64;
    float q1 = g_qkv[base + j],        q2 = g_qkv[base + 32 + j];
    float k1 = g_qkv[base + 1024 + j], k2 = g_qkv[base + 1056 + j];

    float inv = exp2f(-(float)(2 * j) * (13.287712379549449f / 64.f));
    float ang = (float)t * inv, sn, cs;
    sincosf(ang, &sn, &cs);

    const float qs = 0.18033688011112043f;  // 1/8 * log2(e)
    float qr1 = (q1 * cs - q2 * sn) * qs;
    float qr2 = (q2 * cs + q1 * sn) * qs;
    float kr1 = k1 * cs - k2 * sn;
    float kr2 = k2 * cs + k1 * sn;

    int bh = b * 16 + h;
    size_t ob = ((size_t)bh * TT + t) * 128;
    bf16 hh, ll;
    hh = __float2bfloat16(qr1); ll = __float2bfloat16(qr1 - __bfloat162float(hh));
    g_qe[ob + j] = hh;      g_qe[ob + 64 + j] = ll;
    hh = __float2bfloat16(qr2); ll = __float2bfloat16(qr2 - __bfloat162float(hh));
    g_qe[ob + 32 + j] = hh; g_qe[ob + 96 + j] = ll;
    hh = __float2bfloat16(kr1); ll = __float2bfloat16(kr1 - __bfloat162float(hh));
    g_ke[ob + j] = hh;      g_ke[ob + 64 + j] = ll;
    hh = __float2bfloat16(kr2); ll = __float2bfloat16(kr2 - __bfloat162float(hh));
    g_ke[ob + 32 + j] = hh; g_ke[ob + 96 + j] = ll;
}

// ---------------- V transpose to dim-major split ----------------
__global__ void vtrans_kernel() {
    __shared__ float vs[32][65];
    int bh = blockIdx.y, t0 = blockIdx.x * 32;
    int b = bh >> 4, h = bh & 15;
    int tid = threadIdx.x;
#pragma unroll
    for (int i = 0; i < 8; i++) {
        int idx = i * 256 + tid;
        int t = idx >> 6, d = idx & 63;
        vs[t][d] = g_qkv[(size_t)(b * TT + t0 + t) * 3072 + 2048 + h * 64 + d];
    }
    __syncthreads();
    int t = tid & 31;
#pragma unroll
    for (int i = 0; i < 8; i++) {
        int d = i * 8 + (tid >> 5);
        float v = vs[t][d];
        bf16 hh = __float2bfloat16(v);
        bf16 ll = __float2bfloat16(v - __bfloat162float(hh));
        size_t vb = ((size_t)bh * 64 + d) * (2 * TT) + t0 + t;
        g_vt[vb] = hh;
        g_vt[vb + TT] = ll;
    }
}

// ---------------- flash attention, bf16x3 mma, segment-fused, 3-stage ----------------
#define AST 34816   // bytes per stage (Ks 64x136 + Vs 64x136, bf16)
__global__ __launch_bounds__(256) void attn_kernel() {
    extern __shared__ char smraw[];

    const int tid = threadIdx.x, wid = tid >> 5, lane = tid & 31;
    const int g = lane >> 2, q = lane & 3;
    const int bh = blockIdx.y, q0 = blockIdx.x * 128;

    const int krow = (lane & 7) + (lane >> 4) * 8;
    const int kcs  = ((lane >> 3) & 1) * 8;

    const bf16* qbase = g_qe + ((size_t)bh * TT + q0) * 128;
    const bf16* kbase = g_ke + (size_t)bh * TT * 128;
    const bf16* vbase = g_vt + (size_t)bh * 64 * (2 * TT);

    uint32_t qf[8][4];
    {
        int r = wid * 16 + g;
#pragma unroll
        for (int ka = 0; ka < 8; ka++) {
            int c = ka * 16 + 2 * q;
            qf[ka][0] = *(const uint32_t*)&qbase[(size_t)r * 128 + c];
            qf[ka][1] = *(const uint32_t*)&qbase[(size_t)(r + 8) * 128 + c];
            qf[ka][2] = *(const uint32_t*)&qbase[(size_t)r * 128 + c + 8];
            qf[ka][3] = *(const uint32_t*)&qbase[(size_t)(r + 8) * 128 + c + 8];
        }
    }

    float o[8][4];
#pragma unroll
    for (int na = 0; na < 8; na++)
#pragma unroll
        for (int r2 = 0; r2 < 4; r2++) o[na][r2] = 0.f;
    float mrow0 = -1e30f, mrow1 = -1e30f, lr0 = 0.f, lr1 = 0.f;

    const int lrow = tid >> 2;
    const int lp0  = (tid & 3) * 4;

    auto load_tile = [&](int jt, int buf) {
        bf16 (*Ks)[136] = (bf16(*)[136])(smraw + buf * AST);
        bf16 (*Vs)[136] = (bf16(*)[136])(smraw + buf * AST + 17408);
        int j0 = jt * 64;
#pragma unroll
        for (int c2 = 0; c2 < 4; c2++) {
            int part = lp0 + c2;
            cpa16(&Ks[lrow][part * 8], kbase + (size_t)(j0 + lrow) * 128 + part * 8);
            const bf16* vsrc = (part < 8)
                ? (vbase + (size_t)lrow * (2 * TT) + j0 + part * 8)
                : (vbase + (size_t)lrow * (2 * TT) + TT + j0 + (part - 8) * 8);
            cpa16(&Vs[lrow][part * 8], vsrc);
        }
        cp_commit();
    };

    load_tile(0, 0);
    load_tile(1, 1);

    for (int jt = 0; jt < 32; jt++) {
        cp_wait1();
        __syncthreads();
        if (jt + 2 < 32) load_tile(jt + 2, (jt + 2) % 3);
        else cp_commit();

        const int buf = jt % 3;
        const bf16 (*Ks)[136] = (const bf16(*)[136])(smraw + buf * AST);
        const bf16 (*Vs)[136] = (const bf16(*)[136])(smraw + buf * AST + 17408);

        float s[8][4];
#pragma unroll
        for (int na = 0; na < 8; na++)
#pragma unroll
            for (int r2 = 0; r2 < 4; r2++) s[na][r2] = 0.f;

#pragma unroll
        for (int ks = 0; ks < 4; ks++) {
#pragma unroll
            for (int pr = 0; pr < 4; pr++) {
                uint32_t b4h[4], b4l[4];
                ldsm4(b4h, &Ks[pr * 16 + krow][ks * 16 + kcs]);
                ldsm4(b4l, &Ks[pr * 16 + krow][64 + ks * 16 + kcs]);
                mma16816(s[2 * pr],     qf[ks], b4h);
                mma16816(s[2 * pr + 1], qf[ks], b4h + 2);
                mma16816(s[2 * pr],     qf[ks], b4l);
                mma16816(s[2 * pr + 1], qf[ks], b4l + 2);
                mma16816(s[2 * pr],     qf[4 + ks], b4h);
                mma16816(s[2 * pr + 1], qf[4 + ks], b4h + 2);
            }
        }

        float nm0 = mrow0, nm1 = mrow1;
#pragma unroll
        for (int na = 0; na < 8; na++) {
            nm0 = fmaxf(nm0, fmaxf(s[na][0], s[na][1]));
            nm1 = fmaxf(nm1, fmaxf(s[na][2], s[na][3]));
        }
        nm0 = fmaxf(nm0, __shfl_xor_sync(0xffffffffu, nm0, 1));
        nm0 = fmaxf(nm0, __shfl_xor_sync(0xffffffffu, nm0, 2));
        nm1 = fmaxf(nm1, __shfl_xor_sync(0xffffffffu, nm1, 1));
        nm1 = fmaxf(nm1, __shfl_xor_sync(0xffffffffu, nm1, 2));
        float corr0 = ex2(mrow0 - nm0), corr1 = ex2(mrow1 - nm1);
        mrow0 = nm0; mrow1 = nm1;
        lr0 *= corr0; lr1 *= corr1;
#pragma unroll
        for (int na = 0; na < 8; na++) {
            o[na][0] *= corr0; o[na][1] *= corr0;
            o[na][2] *= corr1; o[na][3] *= corr1;
        }

        uint32_t phA[8], phB[8], plA[8], plB[8];
#pragma unroll
        for (int na = 0; na < 8; na++) {
            float p0 = ex2(s[na][0] - nm0), p1 = ex2(s[na][1] - nm0);
            float p2 = ex2(s[na][2] - nm1), p3 = ex2(s[na][3] - nm1);
            lr0 += p0 + p1; lr1 += p2 + p3;
            phA[na] = pack_trunc(p0, p1, plA[na]);
            phB[na] = pack_trunc(p2, p3, plB[na]);
        }

#pragma unroll
        for (int ks = 0; ks < 4; ks++) {
            uint32_t afh[4] = { phA[2 * ks], phB[2 * ks], phA[2 * ks + 1], phB[2 * ks + 1] };
            uint32_t afl[4] = { plA[2 * ks], plB[2 * ks], plA[2 * ks + 1], plB[2 * ks + 1] };
#pragma unroll
            for (int pr = 0; pr < 4; pr++) {
                uint32_t b4h[4], b4l[4];
                ldsm4(b4h, &Vs[pr * 16 + krow][ks * 16 + kcs]);
                ldsm4(b4l, &Vs[pr * 16 + krow][64 + ks * 16 + kcs]);
                mma16816(o[2 * pr],     afh, b4h);
                mma16816(o[2 * pr + 1], afh, b4h + 2);
                mma16816(o[2 * pr],     afh, b4l);
                mma16816(o[2 * pr + 1], afh, b4l + 2);
                mma16816(o[2 * pr],     afl, b4h);
                mma16816(o[2 * pr + 1], afl, b4h + 2);
            }
        }
    }

    lr0 += __shfl_xor_sync(0xffffffffu, lr0, 1);
    lr0 += __shfl_xor_sync(0xffffffffu, lr0, 2);
    lr1 += __shfl_xor_sync(0xffffffffu, lr1, 1);
    lr1 += __shfl_xor_sync(0xffffffffu, lr1, 2);
    float inv0 = 1.f / lr0, inv1 = 1.f / lr1;

    int b = bh >> 4, h = bh & 15;
    int t0 = q0 + wid * 16 + g;
    size_t row0 = (size_t)(b * TT + t0) * 2048;
    size_t row1 = (size_t)(b * TT + t0 + 8) * 2048;
#pragma unroll
    for (int na = 0; na < 8; na++) {
        int c = h * 64 + na * 8 + 2 * q;
        uint32_t lo, hi;
        hi = pack_hi_lo(o[na][0] * inv0, o[na][1] * inv0, lo);
        *(uint32_t*)&g_ye[row0 + c] = hi;
        *(uint32_t*)&g_ye[row0 + 1024 + c] = lo;
        hi = pack_hi_lo(o[na][2] * inv1, o[na][3] * inv1, lo);
        *(uint32_t*)&g_ye[row1 + c] = hi;
        *(uint32_t*)&g_ye[row1 + 1024 + c] = lo;
    }
}

// ---------------- launch ----------------
extern "C" void kernel_launch(void* const* d_in, const int* in_sizes, int n_in,
                              void* d_out, int out_size)
{
    const float* x      = (const float*)d_in[0];
    const float* W_attn = (const float*)d_in[1];
    const float* W_proj = (const float*)d_in[2];
    float* out = (float*)d_out;

    cudaFuncSetAttribute(gemm_bf16x3<0, 3072>, cudaFuncAttributeMaxDynamicSharedMemorySize, 98304);
    cudaFuncSetAttribute(gemm_bf16x3<1, 1024>, cudaFuncAttributeMaxDynamicSharedMemorySize, 98304);
    cudaFuncSetAttribute(attn_kernel, cudaFuncAttributeMaxDynamicSharedMemorySize, 104448);

    conv_x_kernel<<<MB * 1024 / 256, 256>>>(x);
    conv_w_kernel<0><<<dim3(96, 32), 256>>>(W_attn, 3072);
    conv_w_kernel<1><<<dim3(32, 32), 256>>>(W_proj, 1024);
    gemm_bf16x3<0, 3072><<<dim3(24, 64), 256, 98304>>>(nullptr);
    rope_kernel<<<MB * 512 / 256, 256>>>();
    vtrans_kernel<<<dim3(64, 64), 256>>>();
    attn_kernel<<<dim3(16, 64), 256, 104448>>>();
    gemm_bf16x3<1, 1024><<<dim3(8, 64), 256, 98304>>>(out);
}

// round 9
// speedup vs baseline: 1.1369x; 1.0083x over previous
#include <cuda_runtime.h>
#include <cuda_bf16.h>
#include <cstdint>

typedef __nv_bfloat16 bf16;

#define MB 8192       // B*T
#define TT 2048
#define BH 64         // B*H

// ---------------- device scratch ----------------
__device__ bf16  g_xe [(size_t)MB * 2048];        // x split   [hi(1024) | lo(1024)] row-major
__device__ bf16  g_wat[(size_t)3072 * 2048];      // W_attn^T split, n-major
__device__ bf16  g_wpt[(size_t)1024 * 2048];      // W_proj^T split, n-major
__device__ float g_qkv[(size_t)MB * 3072];        // qkv fp32
__device__ bf16  g_qe [(size_t)BH * TT * 128];    // Q rope split [hi(64)|lo(64)], pre-scaled
__device__ bf16  g_ke [(size_t)BH * TT * 128];    // K rope split
__device__ bf16  g_vt [(size_t)BH * 64 * 2 * TT]; // V dim-major [hi(T)|lo(T)] per dim
__device__ bf16  g_ye [(size_t)MB * 2048];        // attention out split

// ---------------- helpers ----------------
__device__ __forceinline__ void cpa16(void* s, const void* g) {
    uint32_t sa = (uint32_t)__cvta_generic_to_shared(s);
    asm volatile("cp.async.cg.shared.global [%0], [%1], 16;\n" :: "r"(sa), "l"(g));
}
__device__ __forceinline__ void cp_commit() { asm volatile("cp.async.commit_group;\n"); }
__device__ __forceinline__ void cp_wait1()  { asm volatile("cp.async.wait_group 1;\n"); }
__device__ __forceinline__ void cp_wait2()  { asm volatile("cp.async.wait_group 2;\n"); }

__device__ __forceinline__ void ldsm4(uint32_t* r, const void* p) {
    uint32_t a = (uint32_t)__cvta_generic_to_shared(p);
    asm volatile("ldmatrix.sync.aligned.m8n8.x4.shared.b16 {%0,%1,%2,%3}, [%4];"
                 : "=r"(r[0]), "=r"(r[1]), "=r"(r[2]), "=r"(r[3]) : "r"(a));
}

__device__ __forceinline__ void mma16816(float* c, const uint32_t* a, const uint32_t* b) {
    asm volatile("mma.sync.aligned.m16n8k16.row.col.f32.bf16.bf16.f32 "
        "{%0,%1,%2,%3}, {%4,%5,%6,%7}, {%8,%9}, {%0,%1,%2,%3};"
        : "+f"(c[0]), "+f"(c[1]), "+f"(c[2]), "+f"(c[3])
        : "r"(a[0]), "r"(a[1]), "r"(a[2]), "r"(a[3]), "r"(b[0]), "r"(b[1]));
}

__device__ __forceinline__ float ex2(float x) {
    float y; asm("ex2.approx.f32 %0, %1;" : "=f"(y) : "f"(x)); return y;
}

// rn-based split (used outside hot loops)
__device__ __forceinline__ uint32_t pack_hi_lo(float a, float b, uint32_t& lo) {
    bf16 ha = __float2bfloat16(a), hb = __float2bfloat16(b);
    bf16 la = __float2bfloat16(a - __bfloat162float(ha));
    bf16 lb = __float2bfloat16(b - __bfloat162float(hb));
    __nv_bfloat162 h2; h2.x = ha; h2.y = hb;
    __nv_bfloat162 l2; l2.x = la; l2.y = lb;
    lo = *(uint32_t*)&l2;
    return *(uint32_t*)&h2;
}

// truncation-based split: hi = exact top bits (bitmask), lo = residual
__device__ __forceinline__ uint32_t pack_trunc(float a, float b, uint32_t& lo) {
    uint32_t ha = __float_as_uint(a) & 0xFFFF0000u;
    uint32_t hb = __float_as_uint(b) & 0xFFFF0000u;
    uint32_t hi;
    asm("prmt.b32 %0, %1, %2, 0x7632;" : "=r"(hi) : "r"(ha), "r"(hb));
    float la = a - __uint_as_float(ha);
    float lb = b - __uint_as_float(hb);
    asm("cvt.rn.bf16x2.f32 %0, %1, %2;" : "=r"(lo) : "f"(lb), "f"(la));
    return hi;
}

// ---------------- conversion kernels ----------------
__global__ void conv_x_kernel(const float* __restrict__ x) {
    int idx = blockIdx.x * 256 + threadIdx.x;
    if (idx >= MB * 1024) return;
    int m = idx >> 10, c = idx & 1023;
    float v = x[idx];
    bf16 h = __float2bfloat16(v);
    bf16 l = __float2bfloat16(v - __bfloat162float(h));
    g_xe[(size_t)m * 2048 + c] = h;
    g_xe[(size_t)m * 2048 + 1024 + c] = l;
}

template <int WSEL>
__global__ void conv_w_kernel(const float* __restrict__ W, int N) {
    bf16* dst = WSEL ? g_wpt : g_wat;
    __shared__ float ws[32][33];
    int n0 = blockIdx.x * 32, k0 = blockIdx.y * 32;
    int tx = threadIdx.x & 31, ty = threadIdx.x >> 5;
#pragma unroll
    for (int i = 0; i < 4; i++) {
        int k = k0 + ty + i * 8;
        ws[ty + i * 8][tx] = W[(size_t)k * N + n0 + tx];
    }
    __syncthreads();
#pragma unroll
    for (int i = 0; i < 4; i++) {
        int n = n0 + ty + i * 8, k = k0 + tx;
        float v = ws[tx][ty + i * 8];
        bf16 h = __float2bfloat16(v);
        bf16 l = __float2bfloat16(v - __bfloat162float(h));
        dst[(size_t)n * 2048 + k] = h;
        dst[(size_t)n * 2048 + 1024 + k] = l;
    }
}

// ---------------- bf16x3 GEMM, segment-fused: 64 k16 steps, 4-stage, single-sync ----------------
// smem per stage: Ahi/Alo/Bhi/Blo, each 128x16 (+8 pad) bf16
#define GST 12288   // bf16 elems per stage: 4 * 128 * 24
template <int MODE, int N>
__global__ __launch_bounds__(256, 2) void gemm_bf16x3(float* __restrict__ Cext) {
    const bf16* A  = MODE ? g_ye  : g_xe;
    const bf16* Bt = MODE ? g_wpt : g_wat;
    float*      C  = MODE ? Cext  : g_qkv;

    extern __shared__ bf16 sm[];   // 4 stages x GST

    const int tid = threadIdx.x;
    const int m0 = blockIdx.y * 128, n0 = blockIdx.x * 128;
    const int wid = tid >> 5, lane = tid & 31, g = lane >> 2, q = lane & 3;
    const int wm = (wid & 1) * 64, wn = (wid >> 1) * 32;

    const int arow = (lane & 7) + ((lane >> 3) & 1) * 8;
    const int acs  = (lane >> 4) * 8;
    const int brow = (lane & 7) + (lane >> 4) * 8;
    const int bcs  = ((lane >> 3) & 1) * 8;

    float acc[4][4][4];
#pragma unroll
    for (int i = 0; i < 4; i++)
#pragma unroll
        for (int j = 0; j < 4; j++)
#pragma unroll
            for (int r = 0; r < 4; r++) acc[i][j][r] = 0.f;

    const int lrow = tid >> 1;          // 0..127
    const int lhalf = (tid & 1) * 8;    // which 16B of the 32B row

    auto load_tile = [&](int t, int stage) {
        const int kk = t * 16;
        bf16* st = sm + stage * GST;
        const bf16* arow_p = A  + (size_t)(m0 + lrow) * 2048 + kk + lhalf;
        const bf16* brow_p = Bt + (size_t)(n0 + lrow) * 2048 + kk + lhalf;
        cpa16(st +        lrow * 24 + lhalf, arow_p);          // Ahi
        cpa16(st + 3072 + lrow * 24 + lhalf, arow_p + 1024);   // Alo
        cpa16(st + 6144 + lrow * 24 + lhalf, brow_p);          // Bhi
        cpa16(st + 9216 + lrow * 24 + lhalf, brow_p + 1024);   // Blo
        cp_commit();
    };

    load_tile(0, 0);
    load_tile(1, 1);
    load_tile(2, 2);

    for (int i = 0; i < 64; i++) {
        cp_wait2();
        __syncthreads();            // single barrier per iteration

        const bf16* st = sm + (i & 3) * GST;
        const bf16 (*Ah)[24] = (const bf16(*)[24])(st);
        const bf16 (*Al)[24] = (const bf16(*)[24])(st + 3072);
        const bf16 (*Bh)[24] = (const bf16(*)[24])(st + 6144);
        const bf16 (*Bl)[24] = (const bf16(*)[24])(st + 9216);

        // fragment loads first: feed tensor pipe ASAP
        uint32_t ah[4][4], al[4][4], bh[2][4], bl[2][4];
#pragma unroll
        for (int ma = 0; ma < 4; ma++) ldsm4(ah[ma], &Ah[wm + ma * 16 + arow][acs]);
        ldsm4(bh[0], &Bh[wn + 0  + brow][bcs]);
        ldsm4(bh[1], &Bh[wn + 16 + brow][bcs]);
        ldsm4(bl[0], &Bl[wn + 0  + brow][bcs]);
        ldsm4(bl[1], &Bl[wn + 16 + brow][bcs]);
#pragma unroll
        for (int ma = 0; ma < 4; ma++) ldsm4(al[ma], &Al[wm + ma * 16 + arow][acs]);

        // prefetch next tile (writes stage (i+3)&3 == (i-1)&3 — safe post-barrier)
        if (i + 3 < 64) load_tile(i + 3, (i + 3) & 3);
        else cp_commit();

        // seg 0: Ahi*Bhi
#pragma unroll
        for (int na = 0; na < 4; na++) {
            const uint32_t* bb = &bh[na >> 1][(na & 1) * 2];
#pragma unroll
            for (int ma = 0; ma < 4; ma++) mma16816(acc[ma][na], ah[ma], bb);
        }
        // seg 1: Ahi*Blo
#pragma unroll
        for (int na = 0; na < 4; na++) {
            const uint32_t* bb = &bl[na >> 1][(na & 1) * 2];
#pragma unroll
            for (int ma = 0; ma < 4; ma++) mma16816(acc[ma][na], ah[ma], bb);
        }
        // seg 2: Alo*Bhi
#pragma unroll
        for (int na = 0; na < 4; na++) {
            const uint32_t* bb = &bh[na >> 1][(na & 1) * 2];
#pragma unroll
            for (int ma = 0; ma < 4; ma++) mma16816(acc[ma][na], al[ma], bb);
        }
    }

#pragma unroll
    for (int ma = 0; ma < 4; ma++) {
        int r = m0 + wm + ma * 16 + g;
#pragma unroll
        for (int na = 0; na < 4; na++) {
            int c = n0 + wn + na * 8 + 2 * q;
            *(float2*)&C[(size_t)r * N + c]       = make_float2(acc[ma][na][0], acc[ma][na][1]);
            *(float2*)&C[(size_t)(r + 8) * N + c] = make_float2(acc[ma][na][2], acc[ma][na][3]);
        }
    }
}

// ---------------- RoPE (Q,K), paired halves; Q pre-scaled by 0.125*log2(e) ----------------
__global__ void rope_kernel() {
    int idx = blockIdx.x * 256 + threadIdx.x;        // over B*T*H*32 = 4194304
    if (idx >= MB * 512) return;
    int j = idx & 31, h = (idx >> 5) & 15, t = (idx >> 9) & 2047, b = idx >> 20;

    size_t base = (size_t)(b * TT + t) * 3072 + h * 64;
    float q1 = g_qkv[base + j],        q2 = g_qkv[base + 32 + j];
    float k1 = g_qkv[base + 1024 + j], k2 = g_qkv[base + 1056 + j];

    float inv = exp2f(-(float)(2 * j) * (13.287712379549449f / 64.f));
    float ang = (float)t * inv, sn, cs;
    sincosf(ang, &sn, &cs);

    const float qs = 0.18033688011112043f;  // 1/8 * log2(e)
    float qr1 = (q1 * cs - q2 * sn) * qs;
    float qr2 = (q2 * cs + q1 * sn) * qs;
    float kr1 = k1 * cs - k2 * sn;
    float kr2 = k2 * cs + k1 * sn;

    int bh = b * 16 + h;
    size_t ob = ((size_t)bh * TT + t) * 128;
    bf16 hh, ll;
    hh = __float2bfloat16(qr1); ll = __float2bfloat16(qr1 - __bfloat162float(hh));
    g_qe[ob + j] = hh;      g_qe[ob + 64 + j] = ll;
    hh = __float2bfloat16(qr2); ll = __float2bfloat16(qr2 - __bfloat162float(hh));
    g_qe[ob + 32 + j] = hh; g_qe[ob + 96 + j] = ll;
    hh = __float2bfloat16(kr1); ll = __float2bfloat16(kr1 - __bfloat162float(hh));
    g_ke[ob + j] = hh;      g_ke[ob + 64 + j] = ll;
    hh = __float2bfloat16(kr2); ll = __float2bfloat16(kr2 - __bfloat162float(hh));
    g_ke[ob + 32 + j] = hh; g_ke[ob + 96 + j] = ll;
}

// ---------------- V transpose to dim-major split ----------------
__global__ void vtrans_kernel() {
    __shared__ float vs[32][65];
    int bh = blockIdx.y, t0 = blockIdx.x * 32;
    int b = bh >> 4, h = bh & 15;
    int tid = threadIdx.x;
#pragma unroll
    for (int i = 0; i < 8; i++) {
        int idx = i * 256 + tid;
        int t = idx >> 6, d = idx & 63;
        vs[t][d] = g_qkv[(size_t)(b * TT + t0 + t) * 3072 + 2048 + h * 64 + d];
    }
    __syncthreads();
    int t = tid & 31;
#pragma unroll
    for (int i = 0; i < 8; i++) {
        int d = i * 8 + (tid >> 5);
        float v = vs[t][d];
        bf16 hh = __float2bfloat16(v);
        bf16 ll = __float2bfloat16(v - __bfloat162float(hh));
        size_t vb = ((size_t)bh * 64 + d) * (2 * TT) + t0 + t;
        g_vt[vb] = hh;
        g_vt[vb + TT] = ll;
    }
}

// ---------------- flash attention, bf16x3 mma, segment-fused, 3-stage ----------------
#define AST 34816   // bytes per stage (Ks 64x136 + Vs 64x136, bf16)
__global__ __launch_bounds__(256) void attn_kernel() {
    extern __shared__ char smraw[];

    const int tid = threadIdx.x, wid = tid >> 5, lane = tid & 31;
    const int g = lane >> 2, q = lane & 3;
    const int bh = blockIdx.y, q0 = blockIdx.x * 128;

    const int krow = (lane & 7) + (lane >> 4) * 8;
    const int kcs  = ((lane >> 3) & 1) * 8;

    const bf16* qbase = g_qe + ((size_t)bh * TT + q0) * 128;
    const bf16* kbase = g_ke + (size_t)bh * TT * 128;
    const bf16* vbase = g_vt + (size_t)bh * 64 * (2 * TT);

    uint32_t qf[8][4];
    {
        int r = wid * 16 + g;
#pragma unroll
        for (int ka = 0; ka < 8; ka++) {
            int c = ka * 16 + 2 * q;
            qf[ka][0] = *(const uint32_t*)&qbase[(size_t)r * 128 + c];
            qf[ka][1] = *(const uint32_t*)&qbase[(size_t)(r + 8) * 128 + c];
            qf[ka][2] = *(const uint32_t*)&qbase[(size_t)r * 128 + c + 8];
            qf[ka][3] = *(const uint32_t*)&qbase[(size_t)(r + 8) * 128 + c + 8];
        }
    }

    float o[8][4];
#pragma unroll
    for (int na = 0; na < 8; na++)
#pragma unroll
        for (int r2 = 0; r2 < 4; r2++) o[na][r2] = 0.f;
    float mrow0 = -1e30f, mrow1 = -1e30f, lr0 = 0.f, lr1 = 0.f;

    const int lrow = tid >> 2;
    const int lp0  = (tid & 3) * 4;

    auto load_tile = [&](int jt, int buf) {
        bf16 (*Ks)[136] = (bf16(*)[136])(smraw + buf * AST);
        bf16 (*Vs)[136] = (bf16(*)[136])(smraw + buf * AST + 17408);
        int j0 = jt * 64;
#pragma unroll
        for (int c2 = 0; c2 < 4; c2++) {
            int part = lp0 + c2;
            cpa16(&Ks[lrow][part * 8], kbase + (size_t)(j0 + lrow) * 128 + part * 8);
            const bf16* vsrc = (part < 8)
                ? (vbase + (size_t)lrow * (2 * TT) + j0 + part * 8)
                : (vbase + (size_t)lrow * (2 * TT) + TT + j0 + (part - 8) * 8);
            cpa16(&Vs[lrow][part * 8], vsrc);
        }
        cp_commit();
    };

    load_tile(0, 0);
    load_tile(1, 1);

    for (int jt = 0; jt < 32; jt++) {
        cp_wait1();
        __syncthreads();
        if (jt + 2 < 32) load_tile(jt + 2, (jt + 2) % 3);
        else cp_commit();

        const int buf = jt % 3;
        const bf16 (*Ks)[136] = (const bf16(*)[136])(smraw + buf * AST);
        const bf16 (*Vs)[136] = (const bf16(*)[136])(smraw + buf * AST + 17408);

        float s[8][4];
#pragma unroll
        for (int na = 0; na < 8; na++)
#pragma unroll
            for (int r2 = 0; r2 < 4; r2++) s[na][r2] = 0.f;

#pragma unroll
        for (int ks = 0; ks < 4; ks++) {
#pragma unroll
            for (int pr = 0; pr < 4; pr++) {
                uint32_t b4h[4], b4l[4];
                ldsm4(b4h, &Ks[pr * 16 + krow][ks * 16 + kcs]);
                ldsm4(b4l, &Ks[pr * 16 + krow][64 + ks * 16 + kcs]);
                mma16816(s[2 * pr],     qf[ks], b4h);
                mma16816(s[2 * pr + 1], qf[ks], b4h + 2);
                mma16816(s[2 * pr],     qf[ks], b4l);
                mma16816(s[2 * pr + 1], qf[ks], b4l + 2);
                mma16816(s[2 * pr],     qf[4 + ks], b4h);
                mma16816(s[2 * pr + 1], qf[4 + ks], b4h + 2);
            }
        }

        float nm0 = mrow0, nm1 = mrow1;
#pragma unroll
        for (int na = 0; na < 8; na++) {
            nm0 = fmaxf(nm0, fmaxf(s[na][0], s[na][1]));
            nm1 = fmaxf(nm1, fmaxf(s[na][2], s[na][3]));
        }
        nm0 = fmaxf(nm0, __shfl_xor_sync(0xffffffffu, nm0, 1));
        nm0 = fmaxf(nm0, __shfl_xor_sync(0xffffffffu, nm0, 2));
        nm1 = fmaxf(nm1, __shfl_xor_sync(0xffffffffu, nm1, 1));
        nm1 = fmaxf(nm1, __shfl_xor_sync(0xffffffffu, nm1, 2));
        float corr0 = ex2(mrow0 - nm0), corr1 = ex2(mrow1 - nm1);
        mrow0 = nm0; mrow1 = nm1;
        lr0 *= corr0; lr1 *= corr1;
#pragma unroll
        for (int na = 0; na < 8; na++) {
            o[na][0] *= corr0; o[na][1] *= corr0;
            o[na][2] *= corr1; o[na][3] *= corr1;
        }

        uint32_t phA[8], phB[8], plA[8], plB[8];
#pragma unroll
        for (int na = 0; na < 8; na++) {
            float p0 = ex2(s[na][0] - nm0), p1 = ex2(s[na][1] - nm0);
            float p2 = ex2(s[na][2] - nm1), p3 = ex2(s[na][3] - nm1);
            lr0 += p0 + p1; lr1 += p2 + p3;
            phA[na] = pack_trunc(p0, p1, plA[na]);
            phB[na] = pack_trunc(p2, p3, plB[na]);
        }

#pragma unroll
        for (int ks = 0; ks < 4; ks++) {
            uint32_t afh[4] = { phA[2 * ks], phB[2 * ks], phA[2 * ks + 1], phB[2 * ks + 1] };
            uint32_t afl[4] = { plA[2 * ks], plB[2 * ks], plA[2 * ks + 1], plB[2 * ks + 1] };
#pragma unroll
            for (int pr = 0; pr < 4; pr++) {
                uint32_t b4h[4], b4l[4];
                ldsm4(b4h, &Vs[pr * 16 + krow][ks * 16 + kcs]);
                ldsm4(b4l, &Vs[pr * 16 + krow][64 + ks * 16 + kcs]);
                mma16816(o[2 * pr],     afh, b4h);
                mma16816(o[2 * pr + 1], afh, b4h + 2);
                mma16816(o[2 * pr],     afh, b4l);
                mma16816(o[2 * pr + 1], afh, b4l + 2);
                mma16816(o[2 * pr],     afl, b4h);
                mma16816(o[2 * pr + 1], afl, b4h + 2);
            }
        }
    }

    lr0 += __shfl_xor_sync(0xffffffffu, lr0, 1);
    lr0 += __shfl_xor_sync(0xffffffffu, lr0, 2);
    lr1 += __shfl_xor_sync(0xffffffffu, lr1, 1);
    lr1 += __shfl_xor_sync(0xffffffffu, lr1, 2);
    float inv0 = 1.f / lr0, inv1 = 1.f / lr1;

    int b = bh >> 4, h = bh & 15;
    int t0 = q0 + wid * 16 + g;
    size_t row0 = (size_t)(b * TT + t0) * 2048;
    size_t row1 = (size_t)(b * TT + t0 + 8) * 2048;
#pragma unroll
    for (int na = 0; na < 8; na++) {
        int c = h * 64 + na * 8 + 2 * q;
        uint32_t lo, hi;
        hi = pack_hi_lo(o[na][0] * inv0, o[na][1] * inv0, lo);
        *(uint32_t*)&g_ye[row0 + c] = hi;
        *(uint32_t*)&g_ye[row0 + 1024 + c] = lo;
        hi = pack_hi_lo(o[na][2] * inv1, o[na][3] * inv1, lo);
        *(uint32_t*)&g_ye[row1 + c] = hi;
        *(uint32_t*)&g_ye[row1 + 1024 + c] = lo;
    }
}

// ---------------- launch ----------------
extern "C" void kernel_launch(void* const* d_in, const int* in_sizes, int n_in,
                              void* d_out, int out_size)
{
    const float* x      = (const float*)d_in[0];
    const float* W_attn = (const float*)d_in[1];
    const float* W_proj = (const float*)d_in[2];
    float* out = (float*)d_out;

    cudaFuncSetAttribute(gemm_bf16x3<0, 3072>, cudaFuncAttributeMaxDynamicSharedMemorySize, 98304);
    cudaFuncSetAttribute(gemm_bf16x3<1, 1024>, cudaFuncAttributeMaxDynamicSharedMemorySize, 98304);
    cudaFuncSetAttribute(attn_kernel, cudaFuncAttributeMaxDynamicSharedMemorySize, 104448);

    conv_x_kernel<<<MB * 1024 / 256, 256>>>(x);
    conv_w_kernel<0><<<dim3(96, 32), 256>>>(W_attn, 3072);
    conv_w_kernel<1><<<dim3(32, 32), 256>>>(W_proj, 1024);
    gemm_bf16x3<0, 3072><<<dim3(24, 64), 256, 98304>>>(nullptr);
    rope_kernel<<<MB * 512 / 256, 256>>>();
    vtrans_kernel<<<dim3(64, 64), 256>>>();
    attn_kernel<<<dim3(16, 64), 256, 104448>>>();
    gemm_bf16x3<1, 1024><<<dim3(8, 64), 256, 98304>>>(out);
}

// round 10
// speedup vs baseline: 1.1683x; 1.0277x over previous
#include <cuda_runtime.h>
#include <cuda_bf16.h>
#include <cstdint>

typedef __nv_bfloat16 bf16;

#define MB 8192       // B*T
#define TT 2048
#define BH 64         // B*H

// ---------------- device scratch ----------------
__device__ bf16  g_xe [(size_t)MB * 2048];        // x split   [hi(1024) | lo(1024)] row-major
__device__ bf16  g_wat[(size_t)3072 * 2048];      // W_attn^T split, n-major
__device__ bf16  g_wpt[(size_t)1024 * 2048];      // W_proj^T split, n-major
__device__ float g_qkv[(size_t)MB * 3072];        // qkv fp32
__device__ bf16  g_qe [(size_t)BH * TT * 128];    // Q rope split [hi(64)|lo(64)], pre-scaled
__device__ bf16  g_ke [(size_t)BH * TT * 128];    // K rope split
__device__ bf16  g_vt [(size_t)BH * 64 * 2 * TT]; // V dim-major [hi(T)|lo(T)] per dim
__device__ bf16  g_ye [(size_t)MB * 2048];        // attention out split

// ---------------- helpers ----------------
__device__ __forceinline__ void cpa16(void* s, const void* g) {
    uint32_t sa = (uint32_t)__cvta_generic_to_shared(s);
    asm volatile("cp.async.cg.shared.global [%0], [%1], 16;\n" :: "r"(sa), "l"(g));
}
__device__ __forceinline__ void cp_commit() { asm volatile("cp.async.commit_group;\n"); }
__device__ __forceinline__ void cp_wait1()  { asm volatile("cp.async.wait_group 1;\n"); }
__device__ __forceinline__ void cp_wait2()  { asm volatile("cp.async.wait_group 2;\n"); }

__device__ __forceinline__ void ldsm4(uint32_t* r, const void* p) {
    uint32_t a = (uint32_t)__cvta_generic_to_shared(p);
    asm volatile("ldmatrix.sync.aligned.m8n8.x4.shared.b16 {%0,%1,%2,%3}, [%4];"
                 : "=r"(r[0]), "=r"(r[1]), "=r"(r[2]), "=r"(r[3]) : "r"(a));
}

__device__ __forceinline__ void mma16816(float* c, const uint32_t* a, const uint32_t* b) {
    asm volatile("mma.sync.aligned.m16n8k16.row.col.f32.bf16.bf16.f32 "
        "{%0,%1,%2,%3}, {%4,%5,%6,%7}, {%8,%9}, {%0,%1,%2,%3};"
        : "+f"(c[0]), "+f"(c[1]), "+f"(c[2]), "+f"(c[3])
        : "r"(a[0]), "r"(a[1]), "r"(a[2]), "r"(a[3]), "r"(b[0]), "r"(b[1]));
}

__device__ __forceinline__ float ex2(float x) {
    float y; asm("ex2.approx.f32 %0, %1;" : "=f"(y) : "f"(x)); return y;
}

// rn-based split (used outside hot loops)
__device__ __forceinline__ uint32_t pack_hi_lo(float a, float b, uint32_t& lo) {
    bf16 ha = __float2bfloat16(a), hb = __float2bfloat16(b);
    bf16 la = __float2bfloat16(a - __bfloat162float(ha));
    bf16 lb = __float2bfloat16(b - __bfloat162float(hb));
    __nv_bfloat162 h2; h2.x = ha; h2.y = hb;
    __nv_bfloat162 l2; l2.x = la; l2.y = lb;
    lo = *(uint32_t*)&l2;
    return *(uint32_t*)&h2;
}

// truncation-based split: hi = exact top bits (bitmask), lo = residual
__device__ __forceinline__ uint32_t pack_trunc(float a, float b, uint32_t& lo) {
    uint32_t ha = __float_as_uint(a) & 0xFFFF0000u;
    uint32_t hb = __float_as_uint(b) & 0xFFFF0000u;
    uint32_t hi;
    asm("prmt.b32 %0, %1, %2, 0x7632;" : "=r"(hi) : "r"(ha), "r"(hb));
    float la = a - __uint_as_float(ha);
    float lb = b - __uint_as_float(hb);
    asm("cvt.rn.bf16x2.f32 %0, %1, %2;" : "=r"(lo) : "f"(lb), "f"(la));
    return hi;
}

// ---------------- conversion kernels ----------------
__global__ void conv_x_kernel(const float* __restrict__ x) {
    int idx = blockIdx.x * 256 + threadIdx.x;
    if (idx >= MB * 1024) return;
    int m = idx >> 10, c = idx & 1023;
    float v = x[idx];
    bf16 h = __float2bfloat16(v);
    bf16 l = __float2bfloat16(v - __bfloat162float(h));
    g_xe[(size_t)m * 2048 + c] = h;
    g_xe[(size_t)m * 2048 + 1024 + c] = l;
}

template <int WSEL>
__global__ void conv_w_kernel(const float* __restrict__ W, int N) {
    bf16* dst = WSEL ? g_wpt : g_wat;
    __shared__ float ws[32][33];
    int n0 = blockIdx.x * 32, k0 = blockIdx.y * 32;
    int tx = threadIdx.x & 31, ty = threadIdx.x >> 5;
#pragma unroll
    for (int i = 0; i < 4; i++) {
        int k = k0 + ty + i * 8;
        ws[ty + i * 8][tx] = W[(size_t)k * N + n0 + tx];
    }
    __syncthreads();
#pragma unroll
    for (int i = 0; i < 4; i++) {
        int n = n0 + ty + i * 8, k = k0 + tx;
        float v = ws[tx][ty + i * 8];
        bf16 h = __float2bfloat16(v);
        bf16 l = __float2bfloat16(v - __bfloat162float(h));
        dst[(size_t)n * 2048 + k] = h;
        dst[(size_t)n * 2048 + 1024 + k] = l;
    }
}

// ---------------- bf16x3 GEMM, segment-fused: 64 k16 steps, 4-stage, single-sync ----------------
// smem per stage: Ahi/Alo/Bhi/Blo, each 128x16 (+8 pad) bf16
#define GST 12288   // bf16 elems per stage: 4 * 128 * 24
template <int MODE, int N>
__global__ __launch_bounds__(256, 2) void gemm_bf16x3(float* __restrict__ Cext) {
    const bf16* A  = MODE ? g_ye  : g_xe;
    const bf16* Bt = MODE ? g_wpt : g_wat;
    float*      C  = MODE ? Cext  : g_qkv;

    extern __shared__ bf16 sm[];   // 4 stages x GST

    const int tid = threadIdx.x;
    const int m0 = blockIdx.y * 128, n0 = blockIdx.x * 128;
    const int wid = tid >> 5, lane = tid & 31, g = lane >> 2, q = lane & 3;
    const int wm = (wid & 1) * 64, wn = (wid >> 1) * 32;

    const int arow = (lane & 7) + ((lane >> 3) & 1) * 8;
    const int acs  = (lane >> 4) * 8;
    const int brow = (lane & 7) + (lane >> 4) * 8;
    const int bcs  = ((lane >> 3) & 1) * 8;

    float acc[4][4][4];
#pragma unroll
    for (int i = 0; i < 4; i++)
#pragma unroll
        for (int j = 0; j < 4; j++)
#pragma unroll
            for (int r = 0; r < 4; r++) acc[i][j][r] = 0.f;

    const int lrow = tid >> 1;          // 0..127
    const int lhalf = (tid & 1) * 8;    // which 16B of the 32B row

    auto load_tile = [&](int t, int stage) {
        const int kk = t * 16;
        bf16* st = sm + stage * GST;
        const bf16* arow_p = A  + (size_t)(m0 + lrow) * 2048 + kk + lhalf;
        const bf16* brow_p = Bt + (size_t)(n0 + lrow) * 2048 + kk + lhalf;
        cpa16(st +        lrow * 24 + lhalf, arow_p);          // Ahi
        cpa16(st + 3072 + lrow * 24 + lhalf, arow_p + 1024);   // Alo
        cpa16(st + 6144 + lrow * 24 + lhalf, brow_p);          // Bhi
        cpa16(st + 9216 + lrow * 24 + lhalf, brow_p + 1024);   // Blo
        cp_commit();
    };

    load_tile(0, 0);
    load_tile(1, 1);
    load_tile(2, 2);

    for (int i = 0; i < 64; i++) {
        cp_wait2();
        __syncthreads();            // single barrier per iteration

        const bf16* st = sm + (i & 3) * GST;
        const bf16 (*Ah)[24] = (const bf16(*)[24])(st);
        const bf16 (*Al)[24] = (const bf16(*)[24])(st + 3072);
        const bf16 (*Bh)[24] = (const bf16(*)[24])(st + 6144);
        const bf16 (*Bl)[24] = (const bf16(*)[24])(st + 9216);

        uint32_t ah[4][4], al[4][4], bh[2][4], bl[2][4];
#pragma unroll
        for (int ma = 0; ma < 4; ma++) ldsm4(ah[ma], &Ah[wm + ma * 16 + arow][acs]);
        ldsm4(bh[0], &Bh[wn + 0  + brow][bcs]);
        ldsm4(bh[1], &Bh[wn + 16 + brow][bcs]);
        ldsm4(bl[0], &Bl[wn + 0  + brow][bcs]);
        ldsm4(bl[1], &Bl[wn + 16 + brow][bcs]);
#pragma unroll
        for (int ma = 0; ma < 4; ma++) ldsm4(al[ma], &Al[wm + ma * 16 + arow][acs]);

        if (i + 3 < 64) load_tile(i + 3, (i + 3) & 3);
        else cp_commit();

        // seg 0: Ahi*Bhi
#pragma unroll
        for (int na = 0; na < 4; na++) {
            const uint32_t* bb = &bh[na >> 1][(na & 1) * 2];
#pragma unroll
            for (int ma = 0; ma < 4; ma++) mma16816(acc[ma][na], ah[ma], bb);
        }
        // seg 1: Ahi*Blo
#pragma unroll
        for (int na = 0; na < 4; na++) {
            const uint32_t* bb = &bl[na >> 1][(na & 1) * 2];
#pragma unroll
            for (int ma = 0; ma < 4; ma++) mma16816(acc[ma][na], ah[ma], bb);
        }
        // seg 2: Alo*Bhi
#pragma unroll
        for (int na = 0; na < 4; na++) {
            const uint32_t* bb = &bh[na >> 1][(na & 1) * 2];
#pragma unroll
            for (int ma = 0; ma < 4; ma++) mma16816(acc[ma][na], al[ma], bb);
        }
    }

#pragma unroll
    for (int ma = 0; ma < 4; ma++) {
        int r = m0 + wm + ma * 16 + g;
#pragma unroll
        for (int na = 0; na < 4; na++) {
            int c = n0 + wn + na * 8 + 2 * q;
            *(float2*)&C[(size_t)r * N + c]       = make_float2(acc[ma][na][0], acc[ma][na][1]);
            *(float2*)&C[(size_t)(r + 8) * N + c] = make_float2(acc[ma][na][2], acc[ma][na][3]);
        }
    }
}

// ---------------- RoPE (Q,K), paired halves; Q pre-scaled by 0.125*log2(e) ----------------
__global__ void rope_kernel() {
    int idx = blockIdx.x * 256 + threadIdx.x;        // over B*T*H*32 = 4194304
    if (idx >= MB * 512) return;
    int j = idx & 31, h = (idx >> 5) & 15, t = (idx >> 9) & 2047, b = idx >> 20;

    size_t base = (size_t)(b * TT + t) * 3072 + h * 64;
    float q1 = g_qkv[base + j],        q2 = g_qkv[base + 32 + j];
    float k1 = g_qkv[base + 1024 + j], k2 = g_qkv[base + 1056 + j];

    float inv = exp2f(-(float)(2 * j) * (13.287712379549449f / 64.f));
    float ang = (float)t * inv, sn, cs;
    sincosf(ang, &sn, &cs);

    const float qs = 0.18033688011112043f;  // 1/8 * log2(e)
    float qr1 = (q1 * cs - q2 * sn) * qs;
    float qr2 = (q2 * cs + q1 * sn) * qs;
    float kr1 = k1 * cs - k2 * sn;
    float kr2 = k2 * cs + k1 * sn;

    int bh = b * 16 + h;
    size_t ob = ((size_t)bh * TT + t) * 128;
    bf16 hh, ll;
    hh = __float2bfloat16(qr1); ll = __float2bfloat16(qr1 - __bfloat162float(hh));
    g_qe[ob + j] = hh;      g_qe[ob + 64 + j] = ll;
    hh = __float2bfloat16(qr2); ll = __float2bfloat16(qr2 - __bfloat162float(hh));
    g_qe[ob + 32 + j] = hh; g_qe[ob + 96 + j] = ll;
    hh = __float2bfloat16(kr1); ll = __float2bfloat16(kr1 - __bfloat162float(hh));
    g_ke[ob + j] = hh;      g_ke[ob + 64 + j] = ll;
    hh = __float2bfloat16(kr2); ll = __float2bfloat16(kr2 - __bfloat162float(hh));
    g_ke[ob + 32 + j] = hh; g_ke[ob + 96 + j] = ll;
}

// ---------------- V transpose to dim-major split ----------------
__global__ void vtrans_kernel() {
    __shared__ float vs[32][65];
    int bh = blockIdx.y, t0 = blockIdx.x * 32;
    int b = bh >> 4, h = bh & 15;
    int tid = threadIdx.x;
#pragma unroll
    for (int i = 0; i < 8; i++) {
        int idx = i * 256 + tid;
        int t = idx >> 6, d = idx & 63;
        vs[t][d] = g_qkv[(size_t)(b * TT + t0 + t) * 3072 + 2048 + h * 64 + d];
    }
    __syncthreads();
    int t = tid & 31;
#pragma unroll
    for (int i = 0; i < 8; i++) {
        int d = i * 8 + (tid >> 5);
        float v = vs[t][d];
        bf16 hh = __float2bfloat16(v);
        bf16 ll = __float2bfloat16(v - __bfloat162float(hh));
        size_t vb = ((size_t)bh * 64 + d) * (2 * TT) + t0 + t;
        g_vt[vb] = hh;
        g_vt[vb + TT] = ll;
    }
}

// ---------------- flash attention, bf16x3 mma, FIXED-MAX softmax, 3-stage ----------------
// scores are in log2 domain (scale*log2e folded into Q); softmax is shift-invariant,
// so use constant shift M=24 (score max ~8, 20-sigma safety) — removes running max,
// correction rescale, and all cross-lane shfl from the hot loop.
#define AST 34816   // bytes per stage (Ks 64x136 + Vs 64x136, bf16)
#define SM_SHIFT 24.0f
__global__ __launch_bounds__(256) void attn_kernel() {
    extern __shared__ char smraw[];

    const int tid = threadIdx.x, wid = tid >> 5, lane = tid & 31;
    const int g = lane >> 2, q = lane & 3;
    const int bh = blockIdx.y, q0 = blockIdx.x * 128;

    const int krow = (lane & 7) + (lane >> 4) * 8;
    const int kcs  = ((lane >> 3) & 1) * 8;

    const bf16* qbase = g_qe + ((size_t)bh * TT + q0) * 128;
    const bf16* kbase = g_ke + (size_t)bh * TT * 128;
    const bf16* vbase = g_vt + (size_t)bh * 64 * (2 * TT);

    uint32_t qf[8][4];
    {
        int r = wid * 16 + g;
#pragma unroll
        for (int ka = 0; ka < 8; ka++) {
            int c = ka * 16 + 2 * q;
            qf[ka][0] = *(const uint32_t*)&qbase[(size_t)r * 128 + c];
            qf[ka][1] = *(const uint32_t*)&qbase[(size_t)(r + 8) * 128 + c];
            qf[ka][2] = *(const uint32_t*)&qbase[(size_t)r * 128 + c + 8];
            qf[ka][3] = *(const uint32_t*)&qbase[(size_t)(r + 8) * 128 + c + 8];
        }
    }

    float o[8][4];
#pragma unroll
    for (int na = 0; na < 8; na++)
#pragma unroll
        for (int r2 = 0; r2 < 4; r2++) o[na][r2] = 0.f;
    float lr0 = 0.f, lr1 = 0.f;

    const int lrow = tid >> 2;
    const int lp0  = (tid & 3) * 4;

    auto load_tile = [&](int jt, int buf) {
        bf16 (*Ks)[136] = (bf16(*)[136])(smraw + buf * AST);
        bf16 (*Vs)[136] = (bf16(*)[136])(smraw + buf * AST + 17408);
        int j0 = jt * 64;
#pragma unroll
        for (int c2 = 0; c2 < 4; c2++) {
            int part = lp0 + c2;
            cpa16(&Ks[lrow][part * 8], kbase + (size_t)(j0 + lrow) * 128 + part * 8);
            const bf16* vsrc = (part < 8)
                ? (vbase + (size_t)lrow * (2 * TT) + j0 + part * 8)
                : (vbase + (size_t)lrow * (2 * TT) + TT + j0 + (part - 8) * 8);
            cpa16(&Vs[lrow][part * 8], vsrc);
        }
        cp_commit();
    };

    load_tile(0, 0);
    load_tile(1, 1);

    for (int jt = 0; jt < 32; jt++) {
        cp_wait1();
        __syncthreads();
        if (jt + 2 < 32) load_tile(jt + 2, (jt + 2) % 3);
        else cp_commit();

        const int buf = jt % 3;
        const bf16 (*Ks)[136] = (const bf16(*)[136])(smraw + buf * AST);
        const bf16 (*Vs)[136] = (const bf16(*)[136])(smraw + buf * AST + 17408);

        float s[8][4];
#pragma unroll
        for (int na = 0; na < 8; na++)
#pragma unroll
            for (int r2 = 0; r2 < 4; r2++) s[na][r2] = 0.f;

#pragma unroll
        for (int ks = 0; ks < 4; ks++) {
#pragma unroll
            for (int pr = 0; pr < 4; pr++) {
                uint32_t b4h[4], b4l[4];
                ldsm4(b4h, &Ks[pr * 16 + krow][ks * 16 + kcs]);
                ldsm4(b4l, &Ks[pr * 16 + krow][64 + ks * 16 + kcs]);
                mma16816(s[2 * pr],     qf[ks], b4h);
                mma16816(s[2 * pr + 1], qf[ks], b4h + 2);
                mma16816(s[2 * pr],     qf[ks], b4l);
                mma16816(s[2 * pr + 1], qf[ks], b4l + 2);
                mma16816(s[2 * pr],     qf[4 + ks], b4h);
                mma16816(s[2 * pr + 1], qf[4 + ks], b4h + 2);
            }
        }

        // ---- fixed-shift exp (no max, no rescale, no shfl) ----
        uint32_t phA[8], phB[8], plA[8], plB[8];
#pragma unroll
        for (int na = 0; na < 8; na++) {
            float p0 = ex2(s[na][0] - SM_SHIFT), p1 = ex2(s[na][1] - SM_SHIFT);
            float p2 = ex2(s[na][2] - SM_SHIFT), p3 = ex2(s[na][3] - SM_SHIFT);
            lr0 += p0 + p1; lr1 += p2 + p3;
            phA[na] = pack_trunc(p0, p1, plA[na]);
            phB[na] = pack_trunc(p2, p3, plB[na]);
        }

#pragma unroll
        for (int ks = 0; ks < 4; ks++) {
            uint32_t afh[4] = { phA[2 * ks], phB[2 * ks], phA[2 * ks + 1], phB[2 * ks + 1] };
            uint32_t afl[4] = { plA[2 * ks], plB[2 * ks], plA[2 * ks + 1], plB[2 * ks + 1] };
#pragma unroll
            for (int pr = 0; pr < 4; pr++) {
                uint32_t b4h[4], b4l[4];
                ldsm4(b4h, &Vs[pr * 16 + krow][ks * 16 + kcs]);
                ldsm4(b4l, &Vs[pr * 16 + krow][64 + ks * 16 + kcs]);
                mma16816(o[2 * pr],     afh, b4h);
                mma16816(o[2 * pr + 1], afh, b4h + 2);
                mma16816(o[2 * pr],     afh, b4l);
                mma16816(o[2 * pr + 1], afh, b4l + 2);
                mma16816(o[2 * pr],     afl, b4h);
                mma16816(o[2 * pr + 1], afl, b4h + 2);
            }
        }
    }

    lr0 += __shfl_xor_sync(0xffffffffu, lr0, 1);
    lr0 += __shfl_xor_sync(0xffffffffu, lr0, 2);
    lr1 += __shfl_xor_sync(0xffffffffu, lr1, 1);
    lr1 += __shfl_xor_sync(0xffffffffu, lr1, 2);
    float inv0 = 1.f / lr0, inv1 = 1.f / lr1;

    int b = bh >> 4, h = bh & 15;
    int t0 = q0 + wid * 16 + g;
    size_t row0 = (size_t)(b * TT + t0) * 2048;
    size_t row1 = (size_t)(b * TT + t0 + 8) * 2048;
#pragma unroll
    for (int na = 0; na < 8; na++) {
        int c = h * 64 + na * 8 + 2 * q;
        uint32_t lo, hi;
        hi = pack_hi_lo(o[na][0] * inv0, o[na][1] * inv0, lo);
        *(uint32_t*)&g_ye[row0 + c] = hi;
        *(uint32_t*)&g_ye[row0 + 1024 + c] = lo;
        hi = pack_hi_lo(o[na][2] * inv1, o[na][3] * inv1, lo);
        *(uint32_t*)&g_ye[row1 + c] = hi;
        *(uint32_t*)&g_ye[row1 + 1024 + c] = lo;
    }
}

// ---------------- launch ----------------
extern "C" void kernel_launch(void* const* d_in, const int* in_sizes, int n_in,
                              void* d_out, int out_size)
{
    const float* x      = (const float*)d_in[0];
    const float* W_attn = (const float*)d_in[1];
    const float* W_proj = (const float*)d_in[2];
    float* out = (float*)d_out;

    cudaFuncSetAttribute(gemm_bf16x3<0, 3072>, cudaFuncAttributeMaxDynamicSharedMemorySize, 98304);
    cudaFuncSetAttribute(gemm_bf16x3<1, 1024>, cudaFuncAttributeMaxDynamicSharedMemorySize, 98304);
    cudaFuncSetAttribute(attn_kernel, cudaFuncAttributeMaxDynamicSharedMemorySize, 104448);

    conv_x_kernel<<<MB * 1024 / 256, 256>>>(x);
    conv_w_kernel<0><<<dim3(96, 32), 256>>>(W_attn, 3072);
    conv_w_kernel<1><<<dim3(32, 32), 256>>>(W_proj, 1024);
    gemm_bf16x3<0, 3072><<<dim3(24, 64), 256, 98304>>>(nullptr);
    rope_kernel<<<MB * 512 / 256, 256>>>();
    vtrans_kernel<<<dim3(64, 64), 256>>>();
    attn_kernel<<<dim3(16, 64), 256, 104448>>>();
    gemm_bf16x3<1, 1024><<<dim3(8, 64), 256, 98304>>>(out);
}

// round 11
// speedup vs baseline: 1.1773x; 1.0077x over previous
#include <cuda_runtime.h>
#include <cuda_bf16.h>
#include <cstdint>

typedef __nv_bfloat16 bf16;

#define MB 8192       // B*T
#define TT 2048
#define BH 64         // B*H

// ---------------- device scratch ----------------
__device__ bf16  g_xe [(size_t)MB * 2048];        // x split   [hi(1024) | lo(1024)] row-major
__device__ bf16  g_wat[(size_t)3072 * 2048];      // W_attn^T split, n-major
__device__ bf16  g_wpt[(size_t)1024 * 2048];      // W_proj^T split, n-major
__device__ bf16  g_qe [(size_t)BH * TT * 128];    // Q rope split [hi(64)|lo(64)], pre-scaled
__device__ bf16  g_ke [(size_t)BH * TT * 128];    // K rope split
__device__ bf16  g_vt [(size_t)BH * 64 * 2 * TT]; // V dim-major [hi(T)|lo(T)] per dim
__device__ bf16  g_ye [(size_t)MB * 2048];        // attention out split

// ---------------- helpers ----------------
__device__ __forceinline__ void cpa16(void* s, const void* g) {
    uint32_t sa = (uint32_t)__cvta_generic_to_shared(s);
    asm volatile("cp.async.cg.shared.global [%0], [%1], 16;\n" :: "r"(sa), "l"(g));
}
__device__ __forceinline__ void cp_commit() { asm volatile("cp.async.commit_group;\n"); }
__device__ __forceinline__ void cp_wait1()  { asm volatile("cp.async.wait_group 1;\n"); }
__device__ __forceinline__ void cp_wait2()  { asm volatile("cp.async.wait_group 2;\n"); }

__device__ __forceinline__ void ldsm4(uint32_t* r, const void* p) {
    uint32_t a = (uint32_t)__cvta_generic_to_shared(p);
    asm volatile("ldmatrix.sync.aligned.m8n8.x4.shared.b16 {%0,%1,%2,%3}, [%4];"
                 : "=r"(r[0]), "=r"(r[1]), "=r"(r[2]), "=r"(r[3]) : "r"(a));
}

__device__ __forceinline__ void mma16816(float* c, const uint32_t* a, const uint32_t* b) {
    asm volatile("mma.sync.aligned.m16n8k16.row.col.f32.bf16.bf16.f32 "
        "{%0,%1,%2,%3}, {%4,%5,%6,%7}, {%8,%9}, {%0,%1,%2,%3};"
        : "+f"(c[0]), "+f"(c[1]), "+f"(c[2]), "+f"(c[3])
        : "r"(a[0]), "r"(a[1]), "r"(a[2]), "r"(a[3]), "r"(b[0]), "r"(b[1]));
}

__device__ __forceinline__ float ex2(float x) {
    float y; asm("ex2.approx.f32 %0, %1;" : "=f"(y) : "f"(x)); return y;
}

// rn-based split (used outside hot loops)
__device__ __forceinline__ uint32_t pack_hi_lo(float a, float b, uint32_t& lo) {
    bf16 ha = __float2bfloat16(a), hb = __float2bfloat16(b);
    bf16 la = __float2bfloat16(a - __bfloat162float(ha));
    bf16 lb = __float2bfloat16(b - __bfloat162float(hb));
    __nv_bfloat162 h2; h2.x = ha; h2.y = hb;
    __nv_bfloat162 l2; l2.x = la; l2.y = lb;
    lo = *(uint32_t*)&l2;
    return *(uint32_t*)&h2;
}

// truncation-based split: hi = exact top bits (bitmask), lo = residual
__device__ __forceinline__ uint32_t pack_trunc(float a, float b, uint32_t& lo) {
    uint32_t ha = __float_as_uint(a) & 0xFFFF0000u;
    uint32_t hb = __float_as_uint(b) & 0xFFFF0000u;
    uint32_t hi;
    asm("prmt.b32 %0, %1, %2, 0x7632;" : "=r"(hi) : "r"(ha), "r"(hb));
    float la = a - __uint_as_float(ha);
    float lb = b - __uint_as_float(hb);
    asm("cvt.rn.bf16x2.f32 %0, %1, %2;" : "=r"(lo) : "f"(lb), "f"(la));
    return hi;
}

// ---------------- conversion kernels ----------------
__global__ void conv_x_kernel(const float* __restrict__ x) {
    int idx = blockIdx.x * 256 + threadIdx.x;
    if (idx >= MB * 1024) return;
    int m = idx >> 10, c = idx & 1023;
    float v = x[idx];
    bf16 h = __float2bfloat16(v);
    bf16 l = __float2bfloat16(v - __bfloat162float(h));
    g_xe[(size_t)m * 2048 + c] = h;
    g_xe[(size_t)m * 2048 + 1024 + c] = l;
}

template <int WSEL>
__global__ void conv_w_kernel(const float* __restrict__ W, int N) {
    bf16* dst = WSEL ? g_wpt : g_wat;
    __shared__ float ws[32][33];
    int n0 = blockIdx.x * 32, k0 = blockIdx.y * 32;
    int tx = threadIdx.x & 31, ty = threadIdx.x >> 5;
#pragma unroll
    for (int i = 0; i < 4; i++) {
        int k = k0 + ty + i * 8;
        ws[ty + i * 8][tx] = W[(size_t)k * N + n0 + tx];
    }
    __syncthreads();
#pragma unroll
    for (int i = 0; i < 4; i++) {
        int n = n0 + ty + i * 8, k = k0 + tx;
        float v = ws[tx][ty + i * 8];
        bf16 h = __float2bfloat16(v);
        bf16 l = __float2bfloat16(v - __bfloat162float(h));
        dst[(size_t)n * 2048 + k] = h;
        dst[(size_t)n * 2048 + 1024 + k] = l;
    }
}

// ---------------- bf16x3 GEMM, segment-fused, 4-stage, single-sync ----------------
// MODE 0: A=g_xe, B=g_wat; fused epilogue applies RoPE/transpose and writes
//         g_qe/g_ke/g_vt directly (no fp32 qkv round-trip).
// MODE 1: A=g_ye, B=g_wpt; plain fp32 store to out.
#define GST 12288   // bf16 elems per stage: 4 * 128 * 24
template <int MODE, int N>
__global__ __launch_bounds__(256, 2) void gemm_bf16x3(float* __restrict__ Cext) {
    const bf16* A  = MODE ? g_ye  : g_xe;
    const bf16* Bt = MODE ? g_wpt : g_wat;

    extern __shared__ bf16 sm[];   // 4 stages x GST (reused as fp32 tile in epilogue)

    const int tid = threadIdx.x;
    const int m0 = blockIdx.y * 128, n0 = blockIdx.x * 128;
    const int wid = tid >> 5, lane = tid & 31, g = lane >> 2, q = lane & 3;
    const int wm = (wid & 1) * 64, wn = (wid >> 1) * 32;

    const int arow = (lane & 7) + ((lane >> 3) & 1) * 8;
    const int acs  = (lane >> 4) * 8;
    const int brow = (lane & 7) + (lane >> 4) * 8;
    const int bcs  = ((lane >> 3) & 1) * 8;

    float acc[4][4][4];
#pragma unroll
    for (int i = 0; i < 4; i++)
#pragma unroll
        for (int j = 0; j < 4; j++)
#pragma unroll
            for (int r = 0; r < 4; r++) acc[i][j][r] = 0.f;

    const int lrow = tid >> 1;          // 0..127
    const int lhalf = (tid & 1) * 8;    // which 16B of the 32B row

    auto load_tile = [&](int t, int stage) {
        const int kk = t * 16;
        bf16* st = sm + stage * GST;
        const bf16* arow_p = A  + (size_t)(m0 + lrow) * 2048 + kk + lhalf;
        const bf16* brow_p = Bt + (size_t)(n0 + lrow) * 2048 + kk + lhalf;
        cpa16(st +        lrow * 24 + lhalf, arow_p);          // Ahi
        cpa16(st + 3072 + lrow * 24 + lhalf, arow_p + 1024);   // Alo
        cpa16(st + 6144 + lrow * 24 + lhalf, brow_p);          // Bhi
        cpa16(st + 9216 + lrow * 24 + lhalf, brow_p + 1024);   // Blo
        cp_commit();
    };

    load_tile(0, 0);
    load_tile(1, 1);
    load_tile(2, 2);

    for (int i = 0; i < 64; i++) {
        cp_wait2();
        __syncthreads();            // single barrier per iteration

        const bf16* st = sm + (i & 3) * GST;
        const bf16 (*Ah)[24] = (const bf16(*)[24])(st);
        const bf16 (*Al)[24] = (const bf16(*)[24])(st + 3072);
        const bf16 (*Bh)[24] = (const bf16(*)[24])(st + 6144);
        const bf16 (*Bl)[24] = (const bf16(*)[24])(st + 9216);

        uint32_t ah[4][4], al[4][4], bh[2][4], bl[2][4];
#pragma unroll
        for (int ma = 0; ma < 4; ma++) ldsm4(ah[ma], &Ah[wm + ma * 16 + arow][acs]);
        ldsm4(bh[0], &Bh[wn + 0  + brow][bcs]);
        ldsm4(bh[1], &Bh[wn + 16 + brow][bcs]);
        ldsm4(bl[0], &Bl[wn + 0  + brow][bcs]);
        ldsm4(bl[1], &Bl[wn + 16 + brow][bcs]);
#pragma unroll
        for (int ma = 0; ma < 4; ma++) ldsm4(al[ma], &Al[wm + ma * 16 + arow][acs]);

        if (i + 3 < 64) load_tile(i + 3, (i + 3) & 3);
        else cp_commit();

        // seg 0: Ahi*Bhi
#pragma unroll
        for (int na = 0; na < 4; na++) {
            const uint32_t* bb = &bh[na >> 1][(na & 1) * 2];
#pragma unroll
            for (int ma = 0; ma < 4; ma++) mma16816(acc[ma][na], ah[ma], bb);
        }
        // seg 1: Ahi*Blo
#pragma unroll
        for (int na = 0; na < 4; na++) {
            const uint32_t* bb = &bl[na >> 1][(na & 1) * 2];
#pragma unroll
            for (int ma = 0; ma < 4; ma++) mma16816(acc[ma][na], ah[ma], bb);
        }
        // seg 2: Alo*Bhi
#pragma unroll
        for (int na = 0; na < 4; na++) {
            const uint32_t* bb = &bh[na >> 1][(na & 1) * 2];
#pragma unroll
            for (int ma = 0; ma < 4; ma++) mma16816(acc[ma][na], al[ma], bb);
        }
    }

    if (MODE == 1) {
        // plain fp32 store
#pragma unroll
        for (int ma = 0; ma < 4; ma++) {
            int r = m0 + wm + ma * 16 + g;
#pragma unroll
            for (int na = 0; na < 4; na++) {
                int c = n0 + wn + na * 8 + 2 * q;
                *(float2*)&Cext[(size_t)r * N + c]       = make_float2(acc[ma][na][0], acc[ma][na][1]);
                *(float2*)&Cext[(size_t)(r + 8) * N + c] = make_float2(acc[ma][na][2], acc[ma][na][3]);
            }
        }
        return;
    }

    // ---- MODE 0 fused epilogue: stage tile in smem, then RoPE / transpose ----
    __syncthreads();                       // all mma smem reads done
    float* Cs = (float*)sm;                // 128 x 133 fp32 (68 KB < 96 KB)
#pragma unroll
    for (int ma = 0; ma < 4; ma++) {
        int r = wm + ma * 16 + g;
#pragma unroll
        for (int na = 0; na < 4; na++) {
            int c = wn + na * 8 + 2 * q;
            Cs[r * 133 + c]           = acc[ma][na][0];
            Cs[r * 133 + c + 1]       = acc[ma][na][1];
            Cs[(r + 8) * 133 + c]     = acc[ma][na][2];
            Cs[(r + 8) * 133 + c + 1] = acc[ma][na][3];
        }
    }
    __syncthreads();

    const int bglob  = m0 >> 11;           // batch index
    const int t0     = m0 & 2047;          // token base
    const int region = n0 >> 10;           // 0=q, 1=k, 2=v
    const int nloc   = n0 & 1023;
    const int h0     = nloc >> 6;          // first of two heads in this tile

    if (region < 2) {
        bf16* dst = region ? g_ke : g_qe;
        const float scl = region ? 1.0f : 0.18033688011112043f;  // q: 1/8*log2(e)
        const int j = tid & 31;
        const int rbase = tid >> 5;        // 0..7
        const float inv = exp2f(-(float)(2 * j) * (13.287712379549449f / 64.f));
        for (int pass = 0; pass < 16; pass++) {
            const int r = pass * 8 + rbase;
            const int t = t0 + r;
            float sn, cs;
            sincosf((float)t * inv, &sn, &cs);
#pragma unroll
            for (int hh = 0; hh < 2; hh++) {
                float v1 = Cs[r * 133 + hh * 64 + j];
                float v2 = Cs[r * 133 + hh * 64 + 32 + j];
                float o1 = (v1 * cs - v2 * sn) * scl;
                float o2 = (v2 * cs + v1 * sn) * scl;
                size_t ob = ((size_t)(bglob * 16 + h0 + hh) * TT + t) * 128;
                bf16 bh_, bl_;
                bh_ = __float2bfloat16(o1); bl_ = __float2bfloat16(o1 - __bfloat162float(bh_));
                dst[ob + j] = bh_;      dst[ob + 64 + j] = bl_;
                bh_ = __float2bfloat16(o2); bl_ = __float2bfloat16(o2 - __bfloat162float(bh_));
                dst[ob + 32 + j] = bh_; dst[ob + 96 + j] = bl_;
            }
        }
    } else {
        // v: transpose to dim-major split
        const int j = tid & 31;            // token offset within 32
        const int cbase = (tid >> 5) * 16; // col base
        for (int tpass = 0; tpass < 4; tpass++) {
            const int rl = tpass * 32 + j;
            const int t = t0 + rl;
#pragma unroll
            for (int cc = 0; cc < 16; cc++) {
                const int col = cbase + cc;
                const int hh = col >> 6, d = col & 63;
                float v = Cs[rl * 133 + col];
                size_t vb = ((size_t)(bglob * 16 + h0 + hh) * 64 + d) * (2 * TT);
                bf16 bh_ = __float2bfloat16(v);
                bf16 bl_ = __float2bfloat16(v - __bfloat162float(bh_));
                g_vt[vb + t] = bh_;
                g_vt[vb + TT + t] = bl_;
            }
        }
    }
}

// ---------------- flash attention, bf16x3 mma, FIXED-MAX softmax, 3-stage ----------------
#define AST 34816   // bytes per stage (Ks 64x136 + Vs 64x136, bf16)
#define SM_SHIFT 24.0f
__global__ __launch_bounds__(256) void attn_kernel() {
    extern __shared__ char smraw[];

    const int tid = threadIdx.x, wid = tid >> 5, lane = tid & 31;
    const int g = lane >> 2, q = lane & 3;
    const int bh = blockIdx.y, q0 = blockIdx.x * 128;

    const int krow = (lane & 7) + (lane >> 4) * 8;
    const int kcs  = ((lane >> 3) & 1) * 8;

    const bf16* qbase = g_qe + ((size_t)bh * TT + q0) * 128;
    const bf16* kbase = g_ke + (size_t)bh * TT * 128;
    const bf16* vbase = g_vt + (size_t)bh * 64 * (2 * TT);

    uint32_t qf[8][4];
    {
        int r = wid * 16 + g;
#pragma unroll
        for (int ka = 0; ka < 8; ka++) {
            int c = ka * 16 + 2 * q;
            qf[ka][0] = *(const uint32_t*)&qbase[(size_t)r * 128 + c];
            qf[ka][1] = *(const uint32_t*)&qbase[(size_t)(r + 8) * 128 + c];
            qf[ka][2] = *(const uint32_t*)&qbase[(size_t)r * 128 + c + 8];
            qf[ka][3] = *(const uint32_t*)&qbase[(size_t)(r + 8) * 128 + c + 8];
        }
    }

    float o[8][4];
#pragma unroll
    for (int na = 0; na < 8; na++)
#pragma unroll
        for (int r2 = 0; r2 < 4; r2++) o[na][r2] = 0.f;
    float lr0 = 0.f, lr1 = 0.f;

    const int lrow = tid >> 2;
    const int lp0  = (tid & 3) * 4;

    auto load_tile = [&](int jt, int buf) {
        bf16 (*Ks)[136] = (bf16(*)[136])(smraw + buf * AST);
        bf16 (*Vs)[136] = (bf16(*)[136])(smraw + buf * AST + 17408);
        int j0 = jt * 64;
#pragma unroll
        for (int c2 = 0; c2 < 4; c2++) {
            int part = lp0 + c2;
            cpa16(&Ks[lrow][part * 8], kbase + (size_t)(j0 + lrow) * 128 + part * 8);
            const bf16* vsrc = (part < 8)
                ? (vbase + (size_t)lrow * (2 * TT) + j0 + part * 8)
                : (vbase + (size_t)lrow * (2 * TT) + TT + j0 + (part - 8) * 8);
            cpa16(&Vs[lrow][part * 8], vsrc);
        }
        cp_commit();
    };

    load_tile(0, 0);
    load_tile(1, 1);

    for (int jt = 0; jt < 32; jt++) {
        cp_wait1();
        __syncthreads();
        if (jt + 2 < 32) load_tile(jt + 2, (jt + 2) % 3);
        else cp_commit();

        const int buf = jt % 3;
        const bf16 (*Ks)[136] = (const bf16(*)[136])(smraw + buf * AST);
        const bf16 (*Vs)[136] = (const bf16(*)[136])(smraw + buf * AST + 17408);

        float s[8][4];
#pragma unroll
        for (int na = 0; na < 8; na++)
#pragma unroll
            for (int r2 = 0; r2 < 4; r2++) s[na][r2] = 0.f;

#pragma unroll
        for (int ks = 0; ks < 4; ks++) {
#pragma unroll
            for (int pr = 0; pr < 4; pr++) {
                uint32_t b4h[4], b4l[4];
                ldsm4(b4h, &Ks[pr * 16 + krow][ks * 16 + kcs]);
                ldsm4(b4l, &Ks[pr * 16 + krow][64 + ks * 16 + kcs]);
                mma16816(s[2 * pr],     qf[ks], b4h);
                mma16816(s[2 * pr + 1], qf[ks], b4h + 2);
                mma16816(s[2 * pr],     qf[ks], b4l);
                mma16816(s[2 * pr + 1], qf[ks], b4l + 2);
                mma16816(s[2 * pr],     qf[4 + ks], b4h);
                mma16816(s[2 * pr + 1], qf[4 + ks], b4h + 2);
            }
        }

        // ---- fixed-shift exp (no max, no rescale, no shfl) ----
        uint32_t phA[8], phB[8], plA[8], plB[8];
#pragma unroll
        for (int na = 0; na < 8; na++) {
            float p0 = ex2(s[na][0] - SM_SHIFT), p1 = ex2(s[na][1] - SM_SHIFT);
            float p2 = ex2(s[na][2] - SM_SHIFT), p3 = ex2(s[na][3] - SM_SHIFT);
            lr0 += p0 + p1; lr1 += p2 + p3;
            phA[na] = pack_trunc(p0, p1, plA[na]);
            phB[na] = pack_trunc(p2, p3, plB[na]);
        }

#pragma unroll
        for (int ks = 0; ks < 4; ks++) {
            uint32_t afh[4] = { phA[2 * ks], phB[2 * ks], phA[2 * ks + 1], phB[2 * ks + 1] };
            uint32_t afl[4] = { plA[2 * ks], plB[2 * ks], plA[2 * ks + 1], plB[2 * ks + 1] };
#pragma unroll
            for (int pr = 0; pr < 4; pr++) {
                uint32_t b4h[4], b4l[4];
                ldsm4(b4h, &Vs[pr * 16 + krow][ks * 16 + kcs]);
                ldsm4(b4l, &Vs[pr * 16 + krow][64 + ks * 16 + kcs]);
                mma16816(o[2 * pr],     afh, b4h);
                mma16816(o[2 * pr + 1], afh, b4h + 2);
                mma16816(o[2 * pr],     afh, b4l);
                mma16816(o[2 * pr + 1], afh, b4l + 2);
                mma16816(o[2 * pr],     afl, b4h);
                mma16816(o[2 * pr + 1], afl, b4h + 2);
            }
        }
    }

    lr0 += __shfl_xor_sync(0xffffffffu, lr0, 1);
    lr0 += __shfl_xor_sync(0xffffffffu, lr0, 2);
    lr1 += __shfl_xor_sync(0xffffffffu, lr1, 1);
    lr1 += __shfl_xor_sync(0xffffffffu, lr1, 2);
    float inv0 = 1.f / lr0, inv1 = 1.f / lr1;

    int b = bh >> 4, h = bh & 15;
    int t0 = q0 + wid * 16 + g;
    size_t row0 = (size_t)(b * TT + t0) * 2048;
    size_t row1 = (size_t)(b * TT + t0 + 8) * 2048;
#pragma unroll
    for (int na = 0; na < 8; na++) {
        int c = h * 64 + na * 8 + 2 * q;
        uint32_t lo, hi;
        hi = pack_hi_lo(o[na][0] * inv0, o[na][1] * inv0, lo);
        *(uint32_t*)&g_ye[row0 + c] = hi;
        *(uint32_t*)&g_ye[row0 + 1024 + c] = lo;
        hi = pack_hi_lo(o[na][2] * inv1, o[na][3] * inv1, lo);
        *(uint32_t*)&g_ye[row1 + c] = hi;
        *(uint32_t*)&g_ye[row1 + 1024 + c] = lo;
    }
}

// ---------------- launch ----------------
extern "C" void kernel_launch(void* const* d_in, const int* in_sizes, int n_in,
                              void* d_out, int out_size)
{
    const float* x      = (const float*)d_in[0];
    const float* W_attn = (const float*)d_in[1];
    const float* W_proj = (const float*)d_in[2];
    float* out = (float*)d_out;

    cudaFuncSetAttribute(gemm_bf16x3<0, 3072>, cudaFuncAttributeMaxDynamicSharedMemorySize, 98304);
    cudaFuncSetAttribute(gemm_bf16x3<1, 1024>, cudaFuncAttributeMaxDynamicSharedMemorySize, 98304);
    cudaFuncSetAttribute(attn_kernel, cudaFuncAttributeMaxDynamicSharedMemorySize, 104448);

    conv_x_kernel<<<MB * 1024 / 256, 256>>>(x);
    conv_w_kernel<0><<<dim3(96, 32), 256>>>(W_attn, 3072);
    conv_w_kernel<1><<<dim3(32, 32), 256>>>(W_proj, 1024);
    gemm_bf16x3<0, 3072><<<dim3(24, 64), 256, 98304>>>(nullptr);   // fused rope+vtrans epilogue
    attn_kernel<<<dim3(16, 64), 256, 104448>>>();
    gemm_bf16x3<1, 1024><<<dim3(8, 64), 256, 98304>>>(out);
}

// round 13
// speedup vs baseline: 1.1998x; 1.0190x over previous
#include <cuda_runtime.h>
#include <cuda_bf16.h>
#include <cstdint>

typedef __nv_bfloat16 bf16;

#define MB 8192       // B*T
#define TT 2048
#define BH 64         // B*H

// ---------------- device scratch ----------------
__device__ bf16  g_xe [(size_t)MB * 2048];        // x split   [hi(1024) | lo(1024)] row-major
__device__ bf16  g_wat[(size_t)3072 * 2048];      // W_attn^T split, n-major
__device__ bf16  g_wpt[(size_t)1024 * 2048];      // W_proj^T split, n-major
__device__ bf16  g_qe [(size_t)BH * TT * 128];    // Q rope split [hi(64)|lo(64)], pre-scaled
__device__ bf16  g_ke [(size_t)BH * TT * 128];    // K rope split
__device__ bf16  g_vt [(size_t)BH * 64 * 2 * TT]; // V dim-major [hi(T)|lo(T)] per dim
__device__ bf16  g_ye [(size_t)MB * 2048];        // attention out split
__device__ float2 g_rt[(size_t)TT * 32];          // rope cos/sin table

// ---------------- helpers ----------------
__device__ __forceinline__ void cpa16(void* s, const void* g) {
    uint32_t sa = (uint32_t)__cvta_generic_to_shared(s);
    asm volatile("cp.async.cg.shared.global [%0], [%1], 16;\n" :: "r"(sa), "l"(g));
}
__device__ __forceinline__ void cp_commit() { asm volatile("cp.async.commit_group;\n"); }
__device__ __forceinline__ void cp_wait1()  { asm volatile("cp.async.wait_group 1;\n"); }
__device__ __forceinline__ void cp_wait2()  { asm volatile("cp.async.wait_group 2;\n"); }

__device__ __forceinline__ void ldsm4(uint32_t* r, const void* p) {
    uint32_t a = (uint32_t)__cvta_generic_to_shared(p);
    asm volatile("ldmatrix.sync.aligned.m8n8.x4.shared.b16 {%0,%1,%2,%3}, [%4];"
                 : "=r"(r[0]), "=r"(r[1]), "=r"(r[2]), "=r"(r[3]) : "r"(a));
}

__device__ __forceinline__ void mma16816(float* c, const uint32_t* a, const uint32_t* b) {
    asm volatile("mma.sync.aligned.m16n8k16.row.col.f32.bf16.bf16.f32 "
        "{%0,%1,%2,%3}, {%4,%5,%6,%7}, {%8,%9}, {%0,%1,%2,%3};"
        : "+f"(c[0]), "+f"(c[1]), "+f"(c[2]), "+f"(c[3])
        : "r"(a[0]), "r"(a[1]), "r"(a[2]), "r"(a[3]), "r"(b[0]), "r"(b[1]));
}

__device__ __forceinline__ float ex2(float x) {
    float y; asm("ex2.approx.f32 %0, %1;" : "=f"(y) : "f"(x)); return y;
}

// rn-based split (used outside hot loops)
__device__ __forceinline__ uint32_t pack_hi_lo(float a, float b, uint32_t& lo) {
    bf16 ha = __float2bfloat16(a), hb = __float2bfloat16(b);
    bf16 la = __float2bfloat16(a - __bfloat162float(ha));
    bf16 lb = __float2bfloat16(b - __bfloat162float(hb));
    __nv_bfloat162 h2; h2.x = ha; h2.y = hb;
    __nv_bfloat162 l2; l2.x = la; l2.y = lb;
    lo = *(uint32_t*)&l2;
    return *(uint32_t*)&h2;
}

// truncation-based split: hi = exact top bits (bitmask), lo = residual
__device__ __forceinline__ uint32_t pack_trunc(float a, float b, uint32_t& lo) {
    uint32_t ha = __float_as_uint(a) & 0xFFFF0000u;
    uint32_t hb = __float_as_uint(b) & 0xFFFF0000u;
    uint32_t hi;
    asm("prmt.b32 %0, %1, %2, 0x7632;" : "=r"(hi) : "r"(ha), "r"(hb));
    float la = a - __uint_as_float(ha);
    float lb = b - __uint_as_float(hb);
    asm("cvt.rn.bf16x2.f32 %0, %1, %2;" : "=r"(lo) : "f"(lb), "f"(la));
    return hi;
}

// ---------------- conversion kernels ----------------
__global__ void conv_x_kernel(const float* __restrict__ x) {
    int idx = blockIdx.x * 256 + threadIdx.x;
    if (idx >= MB * 1024) return;
    int m = idx >> 10, c = idx & 1023;
    float v = x[idx];
    bf16 h = __float2bfloat16(v);
    bf16 l = __float2bfloat16(v - __bfloat162float(h));
    g_xe[(size_t)m * 2048 + c] = h;
    g_xe[(size_t)m * 2048 + 1024 + c] = l;
}

template <int WSEL>
__global__ void conv_w_kernel(const float* __restrict__ W, int N) {
    bf16* dst = WSEL ? g_wpt : g_wat;
    __shared__ float ws[32][33];
    int n0 = blockIdx.x * 32, k0 = blockIdx.y * 32;
    int tx = threadIdx.x & 31, ty = threadIdx.x >> 5;
#pragma unroll
    for (int i = 0; i < 4; i++) {
        int k = k0 + ty + i * 8;
        ws[ty + i * 8][tx] = W[(size_t)k * N + n0 + tx];
    }
    __syncthreads();
#pragma unroll
    for (int i = 0; i < 4; i++) {
        int n = n0 + ty + i * 8, k = k0 + tx;
        float v = ws[tx][ty + i * 8];
        bf16 h = __float2bfloat16(v);
        bf16 l = __float2bfloat16(v - __bfloat162float(h));
        dst[(size_t)n * 2048 + k] = h;
        dst[(size_t)n * 2048 + 1024 + k] = l;
    }
}

__global__ void rope_table_kernel() {
    int idx = blockIdx.x * 256 + threadIdx.x;   // over 2048*32
    if (idx >= TT * 32) return;
    int t = idx >> 5, j = idx & 31;
    float inv = exp2f(-(float)(2 * j) * (13.287712379549449f / 64.f));
    float sn, cs;
    sincosf((float)t * inv, &sn, &cs);
    g_rt[idx] = make_float2(cs, sn);
}

// ---------------- bf16x3 GEMM, segment-fused, 4-stage, single-sync ----------------
// MODE 0: A=g_xe, B=g_wat; fused epilogue applies RoPE/transpose and writes
//         g_qe/g_ke/g_vt directly.
// MODE 1: A=g_ye, B=g_wpt; plain fp32 store to out.
#define GST 12288   // bf16 elems per stage: 4 * 128 * 24
template <int MODE, int N>
__global__ __launch_bounds__(256, 2) void gemm_bf16x3(float* __restrict__ Cext) {
    const bf16* A  = MODE ? g_ye  : g_xe;
    const bf16* Bt = MODE ? g_wpt : g_wat;

    extern __shared__ bf16 sm[];   // 4 stages x GST (reused as fp32 tile in epilogue)

    const int tid = threadIdx.x;
    const int m0 = blockIdx.y * 128, n0 = blockIdx.x * 128;
    const int wid = tid >> 5, lane = tid & 31, g = lane >> 2, q = lane & 3;
    const int wm = (wid & 1) * 64, wn = (wid >> 1) * 32;

    const int arow = (lane & 7) + ((lane >> 3) & 1) * 8;
    const int acs  = (lane >> 4) * 8;
    const int brow = (lane & 7) + (lane >> 4) * 8;
    const int bcs  = ((lane >> 3) & 1) * 8;

    float acc[4][4][4];
#pragma unroll
    for (int i = 0; i < 4; i++)
#pragma unroll
        for (int j = 0; j < 4; j++)
#pragma unroll
            for (int r = 0; r < 4; r++) acc[i][j][r] = 0.f;

    const int lrow = tid >> 1;          // 0..127
    const int lhalf = (tid & 1) * 8;    // which 16B of the 32B row

    auto load_tile = [&](int t, int stage) {
        const int kk = t * 16;
        bf16* st = sm + stage * GST;
        const bf16* arow_p = A  + (size_t)(m0 + lrow) * 2048 + kk + lhalf;
        const bf16* brow_p = Bt + (size_t)(n0 + lrow) * 2048 + kk + lhalf;
        cpa16(st +        lrow * 24 + lhalf, arow_p);          // Ahi
        cpa16(st + 3072 + lrow * 24 + lhalf, arow_p + 1024);   // Alo
        cpa16(st + 6144 + lrow * 24 + lhalf, brow_p);          // Bhi
        cpa16(st + 9216 + lrow * 24 + lhalf, brow_p + 1024);   // Blo
        cp_commit();
    };

    load_tile(0, 0);
    load_tile(1, 1);
    load_tile(2, 2);

    for (int i = 0; i < 64; i++) {
        cp_wait2();
        __syncthreads();            // single barrier per iteration

        const bf16* st = sm + (i & 3) * GST;
        const bf16 (*Ah)[24] = (const bf16(*)[24])(st);
        const bf16 (*Al)[24] = (const bf16(*)[24])(st + 3072);
        const bf16 (*Bh)[24] = (const bf16(*)[24])(st + 6144);
        const bf16 (*Bl)[24] = (const bf16(*)[24])(st + 9216);

        uint32_t ah[4][4], al[4][4], bh[2][4], bl[2][4];
#pragma unroll
        for (int ma = 0; ma < 4; ma++) ldsm4(ah[ma], &Ah[wm + ma * 16 + arow][acs]);
        ldsm4(bh[0], &Bh[wn + 0  + brow][bcs]);
        ldsm4(bh[1], &Bh[wn + 16 + brow][bcs]);
        ldsm4(bl[0], &Bl[wn + 0  + brow][bcs]);
        ldsm4(bl[1], &Bl[wn + 16 + brow][bcs]);
#pragma unroll
        for (int ma = 0; ma < 4; ma++) ldsm4(al[ma], &Al[wm + ma * 16 + arow][acs]);

        if (i + 3 < 64) load_tile(i + 3, (i + 3) & 3);
        else cp_commit();

#pragma unroll
        for (int na = 0; na < 4; na++) {
            const uint32_t* bb = &bh[na >> 1][(na & 1) * 2];
#pragma unroll
            for (int ma = 0; ma < 4; ma++) mma16816(acc[ma][na], ah[ma], bb);
        }
#pragma unroll
        for (int na = 0; na < 4; na++) {
            const uint32_t* bb = &bl[na >> 1][(na & 1) * 2];
#pragma unroll
            for (int ma = 0; ma < 4; ma++) mma16816(acc[ma][na], ah[ma], bb);
        }
#pragma unroll
        for (int na = 0; na < 4; na++) {
            const uint32_t* bb = &bh[na >> 1][(na & 1) * 2];
#pragma unroll
            for (int ma = 0; ma < 4; ma++) mma16816(acc[ma][na], al[ma], bb);
        }
    }

    if (MODE == 1) {
#pragma unroll
        for (int ma = 0; ma < 4; ma++) {
            int r = m0 + wm + ma * 16 + g;
#pragma unroll
            for (int na = 0; na < 4; na++) {
                int c = n0 + wn + na * 8 + 2 * q;
                *(float2*)&Cext[(size_t)r * N + c]       = make_float2(acc[ma][na][0], acc[ma][na][1]);
                *(float2*)&Cext[(size_t)(r + 8) * N + c] = make_float2(acc[ma][na][2], acc[ma][na][3]);
            }
        }
        return;
    }

    // ---- MODE 0 fused epilogue: stage tile in smem, then RoPE / transpose ----
    __syncthreads();
    float* Cs = (float*)sm;                // 128 x 133 fp32
#pragma unroll
    for (int ma = 0; ma < 4; ma++) {
        int r = wm + ma * 16 + g;
#pragma unroll
        for (int na = 0; na < 4; na++) {
            int c = wn + na * 8 + 2 * q;
            Cs[r * 133 + c]           = acc[ma][na][0];
            Cs[r * 133 + c + 1]       = acc[ma][na][1];
            Cs[(r + 8) * 133 + c]     = acc[ma][na][2];
            Cs[(r + 8) * 133 + c + 1] = acc[ma][na][3];
        }
    }
    __syncthreads();

    const int bglob  = m0 >> 11;
    const int t0     = m0 & 2047;
    const int region = n0 >> 10;           // 0=q, 1=k, 2=v
    const int nloc   = n0 & 1023;
    const int h0     = nloc >> 6;

    if (region < 2) {
        bf16* dst = region ? g_ke : g_qe;
        const float scl = region ? 1.0f : 0.18033688011112043f;  // q: 1/8*log2(e)
        const int j = tid & 31;
        const int rbase = tid >> 5;
        for (int pass = 0; pass < 16; pass++) {
            const int r = pass * 8 + rbase;
            const int t = t0 + r;
            float2 cssn = g_rt[t * 32 + j];
            float cs = cssn.x, sn = cssn.y;
#pragma unroll
            for (int hh = 0; hh < 2; hh++) {
                float v1 = Cs[r * 133 + hh * 64 + j];
                float v2 = Cs[r * 133 + hh * 64 + 32 + j];
                float o1 = (v1 * cs - v2 * sn) * scl;
                float o2 = (v2 * cs + v1 * sn) * scl;
                size_t ob = ((size_t)(bglob * 16 + h0 + hh) * TT + t) * 128;
                bf16 bh_, bl_;
                bh_ = __float2bfloat16(o1); bl_ = __float2bfloat16(o1 - __bfloat162float(bh_));
                dst[ob + j] = bh_;      dst[ob + 64 + j] = bl_;
                bh_ = __float2bfloat16(o2); bl_ = __float2bfloat16(o2 - __bfloat162float(bh_));
                dst[ob + 32 + j] = bh_; dst[ob + 96 + j] = bl_;
            }
        }
    } else {
        const int j = tid & 31;
        const int cbase = (tid >> 5) * 16;
        for (int tpass = 0; tpass < 4; tpass++) {
            const int rl = tpass * 32 + j;
            const int t = t0 + rl;
#pragma unroll
            for (int cc = 0; cc < 16; cc++) {
                const int col = cbase + cc;
                const int hh = col >> 6, d = col & 63;
                float v = Cs[rl * 133 + col];
                size_t vb = ((size_t)(bglob * 16 + h0 + hh) * 64 + d) * (2 * TT);
                bf16 bh_ = __float2bfloat16(v);
                bf16 bl_ = __float2bfloat16(v - __bfloat162float(bh_));
                g_vt[vb + t] = bh_;
                g_vt[vb + TT + t] = bl_;
            }
        }
    }
}

// ---------------- flash attention, 32 q-rows/warp (256 q/CTA), fixed-max softmax ----------------
#define AST 34816   // bytes per stage (Ks 64x136 + Vs 64x136, bf16)
#define SM_SHIFT 24.0f
__global__ __launch_bounds__(256) void attn_kernel() {
    extern __shared__ char smraw[];

    const int tid = threadIdx.x, wid = tid >> 5, lane = tid & 31;
    const int g = lane >> 2, q = lane & 3;
    const int bh = blockIdx.y, q0 = blockIdx.x * 256;

    const int krow = (lane & 7) + (lane >> 4) * 8;
    const int kcs  = ((lane >> 3) & 1) * 8;

    const bf16* qbase = g_qe + ((size_t)bh * TT + q0) * 128;
    const bf16* kbase = g_ke + (size_t)bh * TT * 128;
    const bf16* vbase = g_vt + (size_t)bh * 64 * (2 * TT);

    // persistent Q fragments: 2 m-atoms x 8 k-atoms (hi 0..3, lo 4..7)
    uint32_t qf[2][8][4];
#pragma unroll
    for (int ma = 0; ma < 2; ma++) {
        int r = wid * 32 + ma * 16 + g;
#pragma unroll
        for (int ka = 0; ka < 8; ka++) {
            int c = ka * 16 + 2 * q;
            qf[ma][ka][0] = *(const uint32_t*)&qbase[(size_t)r * 128 + c];
            qf[ma][ka][1] = *(const uint32_t*)&qbase[(size_t)(r + 8) * 128 + c];
            qf[ma][ka][2] = *(const uint32_t*)&qbase[(size_t)r * 128 + c + 8];
            qf[ma][ka][3] = *(const uint32_t*)&qbase[(size_t)(r + 8) * 128 + c + 8];
        }
    }

    float o[2][8][4];
#pragma unroll
    for (int ma = 0; ma < 2; ma++)
#pragma unroll
        for (int na = 0; na < 8; na++)
#pragma unroll
            for (int r2 = 0; r2 < 4; r2++) o[ma][na][r2] = 0.f;
    float lr[2][2] = {{0.f, 0.f}, {0.f, 0.f}};

    const int lrow = tid >> 2;
    const int lp0  = (tid & 3) * 4;

    auto load_tile = [&](int jt, int buf) {
        bf16 (*Ks)[136] = (bf16(*)[136])(smraw + buf * AST);
        bf16 (*Vs)[136] = (bf16(*)[136])(smraw + buf * AST + 17408);
        int j0 = jt * 64;
#pragma unroll
        for (int c2 = 0; c2 < 4; c2++) {
            int part = lp0 + c2;
            cpa16(&Ks[lrow][part * 8], kbase + (size_t)(j0 + lrow) * 128 + part * 8);
            const bf16* vsrc = (part < 8)
                ? (vbase + (size_t)lrow * (2 * TT) + j0 + part * 8)
                : (vbase + (size_t)lrow * (2 * TT) + TT + j0 + (part - 8) * 8);
            cpa16(&Vs[lrow][part * 8], vsrc);
        }
        cp_commit();
    };

    load_tile(0, 0);
    load_tile(1, 1);

    for (int jt = 0; jt < 32; jt++) {
        cp_wait1();
        __syncthreads();
        if (jt + 2 < 32) load_tile(jt + 2, (jt + 2) % 3);
        else cp_commit();

        const int buf = jt % 3;
        const bf16 (*Ks)[136] = (const bf16(*)[136])(smraw + buf * AST);
        const bf16 (*Vs)[136] = (const bf16(*)[136])(smraw + buf * AST + 17408);

        // process keys in two 32-chunks
#pragma unroll
        for (int cc = 0; cc < 2; cc++) {
            float s[2][4][4];
#pragma unroll
            for (int ma = 0; ma < 2; ma++)
#pragma unroll
                for (int na = 0; na < 4; na++)
#pragma unroll
                    for (int r2 = 0; r2 < 4; r2++) s[ma][na][r2] = 0.f;

            // ---- S = Q @ K^T (bf16x3) over 32 keys ----
            // Ks rows = keys, cols = dims [hi 64 | lo 64]
#pragma unroll
            for (int ks = 0; ks < 4; ks++) {
#pragma unroll
                for (int pr = 0; pr < 2; pr++) {
                    uint32_t b4h[4], b4l[4];
                    ldsm4(b4h, &Ks[cc * 32 + pr * 16 + krow][ks * 16 + kcs]);
                    ldsm4(b4l, &Ks[cc * 32 + pr * 16 + krow][64 + ks * 16 + kcs]);
#pragma unroll
                    for (int ma = 0; ma < 2; ma++) {
                        mma16816(s[ma][2 * pr],     qf[ma][ks], b4h);
                        mma16816(s[ma][2 * pr + 1], qf[ma][ks], b4h + 2);
                        mma16816(s[ma][2 * pr],     qf[ma][ks], b4l);
                        mma16816(s[ma][2 * pr + 1], qf[ma][ks], b4l + 2);
                        mma16816(s[ma][2 * pr],     qf[ma][4 + ks], b4h);
                        mma16816(s[ma][2 * pr + 1], qf[ma][4 + ks], b4h + 2);
                    }
                }
            }

            // ---- fixed-shift exp + pack ----
            uint32_t phA[2][4], phB[2][4], plA[2][4], plB[2][4];
#pragma unroll
            for (int ma = 0; ma < 2; ma++)
#pragma unroll
                for (int na = 0; na < 4; na++) {
                    float p0 = ex2(s[ma][na][0] - SM_SHIFT), p1 = ex2(s[ma][na][1] - SM_SHIFT);
                    float p2 = ex2(s[ma][na][2] - SM_SHIFT), p3 = ex2(s[ma][na][3] - SM_SHIFT);
                    lr[ma][0] += p0 + p1; lr[ma][1] += p2 + p3;
                    phA[ma][na] = pack_trunc(p0, p1, plA[ma][na]);
                    phB[ma][na] = pack_trunc(p2, p3, plB[ma][na]);
                }

            // ---- O += P @ V (bf16x3) over 32 keys ----
            // Vs rows = dims (n), cols = tokens (k) [hi 64 | lo 64]
            // key atom pk covers tokens cc*32 + pk*16 .. +16 (columns!)
#pragma unroll
            for (int pk = 0; pk < 2; pk++) {
                uint32_t afh[2][4], afl[2][4];
#pragma unroll
                for (int ma = 0; ma < 2; ma++) {
                    afh[ma][0] = phA[ma][2 * pk];     afh[ma][1] = phB[ma][2 * pk];
                    afh[ma][2] = phA[ma][2 * pk + 1]; afh[ma][3] = phB[ma][2 * pk + 1];
                    afl[ma][0] = plA[ma][2 * pk];     afl[ma][1] = plB[ma][2 * pk];
                    afl[ma][2] = plA[ma][2 * pk + 1]; afl[ma][3] = plB[ma][2 * pk + 1];
                }
#pragma unroll
                for (int pr = 0; pr < 4; pr++) {
                    uint32_t b4h[4], b4l[4];
                    ldsm4(b4h, &Vs[pr * 16 + krow][cc * 32 + pk * 16 + kcs]);
                    ldsm4(b4l, &Vs[pr * 16 + krow][64 + cc * 32 + pk * 16 + kcs]);
#pragma unroll
                    for (int ma = 0; ma < 2; ma++) {
                        mma16816(o[ma][2 * pr],     afh[ma], b4h);
                        mma16816(o[ma][2 * pr + 1], afh[ma], b4h + 2);
                        mma16816(o[ma][2 * pr],     afh[ma], b4l);
                        mma16816(o[ma][2 * pr + 1], afh[ma], b4l + 2);
                        mma16816(o[ma][2 * pr],     afl[ma], b4h);
                        mma16816(o[ma][2 * pr + 1], afl[ma], b4h + 2);
                    }
                }
            }
        }
    }

    // ---- epilogue ----
    int b = bh >> 4, h = bh & 15;
#pragma unroll
    for (int ma = 0; ma < 2; ma++) {
        float l0 = lr[ma][0], l1 = lr[ma][1];
        l0 += __shfl_xor_sync(0xffffffffu, l0, 1);
        l0 += __shfl_xor_sync(0xffffffffu, l0, 2);
        l1 += __shfl_xor_sync(0xffffffffu, l1, 1);
        l1 += __shfl_xor_sync(0xffffffffu, l1, 2);
        float inv0 = 1.f / l0, inv1 = 1.f / l1;

        int t0 = q0 + wid * 32 + ma * 16 + g;
        size_t row0 = (size_t)(b * TT + t0) * 2048;
        size_t row1 = (size_t)(b * TT + t0 + 8) * 2048;
#pragma unroll
        for (int na = 0; na < 8; na++) {
            int c = h * 64 + na * 8 + 2 * q;
            uint32_t lo, hi;
            hi = pack_hi_lo(o[ma][na][0] * inv0, o[ma][na][1] * inv0, lo);
            *(uint32_t*)&g_ye[row0 + c] = hi;
            *(uint32_t*)&g_ye[row0 + 1024 + c] = lo;
            hi = pack_hi_lo(o[ma][na][2] * inv1, o[ma][na][3] * inv1, lo);
            *(uint32_t*)&g_ye[row1 + c] = hi;
            *(uint32_t*)&g_ye[row1 + 1024 + c] = lo;
        }
    }
}

// ---------------- launch ----------------
extern "C" void kernel_launch(void* const* d_in, const int* in_sizes, int n_in,
                              void* d_out, int out_size)
{
    const float* x      = (const float*)d_in[0];
    const float* W_attn = (const float*)d_in[1];
    const float* W_proj = (const float*)d_in[2];
    float* out = (float*)d_out;

    cudaFuncSetAttribute(gemm_bf16x3<0, 3072>, cudaFuncAttributeMaxDynamicSharedMemorySize, 98304);
    cudaFuncSetAttribute(gemm_bf16x3<1, 1024>, cudaFuncAttributeMaxDynamicSharedMemorySize, 98304);
    cudaFuncSetAttribute(attn_kernel, cudaFuncAttributeMaxDynamicSharedMemorySize, 104448);

    rope_table_kernel<<<TT * 32 / 256, 256>>>();
    conv_x_kernel<<<MB * 1024 / 256, 256>>>(x);
    conv_w_kernel<0><<<dim3(96, 32), 256>>>(W_attn, 3072);
    conv_w_kernel<1><<<dim3(32, 32), 256>>>(W_proj, 1024);
    gemm_bf16x3<0, 3072><<<dim3(24, 64), 256, 98304>>>(nullptr);   // fused rope+vtrans epilogue
    attn_kernel<<<dim3(8, 64), 256, 104448>>>();
    gemm_bf16x3<1, 1024><<<dim3(8, 64), 256, 98304>>>(out);
}